// round 14
// baseline (speedup 1.0000x reference)
#include <cuda_runtime.h>
#include <cuda_fp16.h>
#include <stdint.h>
#include <math.h>

// Problem constants
#define BATCH 8
#define LSEQ 1024
#define DMODEL 1024
#define NHEAD 16
#define HDIM 64
#define DFF 4096
#define MROWS (BATCH * LSEQ)   // 8192
#define ATT_SCALE 0.125f
#define LN_EPS 1e-5f
#define QB (BATCH / 4)            // 2 batches per chunk
#define QROWS (QB * LSEQ)         // 2048 rows per chunk

// ---------------- scratch (device globals; no allocation allowed) ----------
__device__ __half g_qh[MROWS * DMODEL];
__device__ __half g_kvh[MROWS * DMODEL];
__device__ __half g_qph[MROWS * DMODEL];
__device__ __half g_kvph[(size_t)MROWS * 2 * DMODEL];   // packed [row][K|V]
__device__ __half g_atth[MROWS * DMODEL];
__device__ __half g_xh[MROWS * DMODEL];
__device__ __half g_hh[(size_t)MROWS * DFF];
__device__ __half g_wqh[DMODEL * DMODEL];               // [K][N] half
__device__ __half g_wkvh[DMODEL * 2 * DMODEL];          // [K][2N]: Wk|Wv packed
__device__ __half g_woh[DMODEL * DMODEL];
__device__ __half g_w1h[DMODEL * DFF];
__device__ __half g_w2h[DFF * DMODEL];
__device__ float g_bkv[2 * DMODEL];
__device__ float g_y[MROWS * DMODEL];
__device__ float g_x[MROWS * DMODEL];
__device__ int g_allpad[BATCH];
__device__ unsigned char g_emask[BATCH * LSEQ];
__device__ int g_mstride[1];

// ---------------- helpers ----------------------------------------------------
__device__ __forceinline__ void cpa16(uint32_t s, const void* g) {
    asm volatile("cp.async.cg.shared.global [%0], [%1], 16;\n" :: "r"(s), "l"(g));
}
__device__ __forceinline__ void ldmat_x4(uint32_t* r, uint32_t addr) {
    asm volatile("ldmatrix.sync.aligned.m8n8.x4.shared.b16 {%0,%1,%2,%3}, [%4];"
        : "=r"(r[0]), "=r"(r[1]), "=r"(r[2]), "=r"(r[3]) : "r"(addr));
}
__device__ __forceinline__ void ldmat_x4t(uint32_t* r, uint32_t addr) {
    asm volatile("ldmatrix.sync.aligned.m8n8.x4.trans.shared.b16 {%0,%1,%2,%3}, [%4];"
        : "=r"(r[0]), "=r"(r[1]), "=r"(r[2]), "=r"(r[3]) : "r"(addr));
}
__device__ __forceinline__ void mma_f16(float* c, const uint32_t* a, const uint32_t* b) {
    asm volatile(
        "mma.sync.aligned.m16n8k16.row.col.f32.f16.f16.f32 "
        "{%0,%1,%2,%3}, {%4,%5,%6,%7}, {%8,%9}, {%0,%1,%2,%3};"
        : "+f"(c[0]), "+f"(c[1]), "+f"(c[2]), "+f"(c[3])
        : "r"(a[0]), "r"(a[1]), "r"(a[2]), "r"(a[3]), "r"(b[0]), "r"(b[1]));
}

// ---------------- FP16 tensor-core GEMM (128x128 tile, BK=64, trans-B) ------
#define GST 72
#define BST 136
#define A_STAGE (128 * GST * 2)
#define B_STAGE (64 * BST * 2)
#define HG_SMEM (2 * (A_STAGE + B_STAGE))  // 71680 B

__device__ __forceinline__ void hfill(const __half* __restrict__ A,
                                      const __half* __restrict__ Bh, int K, int N,
                                      int rowBlk, int colBlk, int kt,
                                      uint32_t abase, uint32_t bbase, int tid) {
#pragma unroll
    for (int c = tid; c < 1024; c += 256) {
        int row = c >> 3, ch = c & 7;
        cpa16(abase + row * (GST * 2) + ch * 16,
              A + (size_t)(rowBlk + row) * K + kt * 64 + ch * 8);
    }
#pragma unroll
    for (int c = tid; c < 1024; c += 256) {
        int row = c >> 4, ch = c & 15;
        cpa16(bbase + row * (BST * 2) + ch * 16,
              Bh + (size_t)(kt * 64 + row) * N + colBlk + ch * 8);
    }
}

__global__ __launch_bounds__(256, 2) void hgemm(
    const __half* __restrict__ A, const __half* __restrict__ Bh,
    const float* __restrict__ bias, const float* __restrict__ res,
    float* __restrict__ C, __half* __restrict__ Ch,
    int M, int N, int K, int doRelu) {
    extern __shared__ char smraw[];
    const uint32_t sb = (uint32_t)__cvta_generic_to_shared(smraw);
    const uint32_t asb = sb;
    const uint32_t bsb = sb + 2 * A_STAGE;

    const int tid = threadIdx.x;
    const int lane = tid & 31, warp = tid >> 5;
    const int wr = warp & 1, wc = warp >> 1;
    const int g = lane >> 2, tg = lane & 3;
    const int grp = lane >> 3, r8 = lane & 7;
    const int rowBlk = blockIdx.y * 128, colBlk = blockIdx.x * 128;

    float acc[4][4][4];
#pragma unroll
    for (int i = 0; i < 4; i++)
#pragma unroll
        for (int j = 0; j < 4; j++)
#pragma unroll
            for (int v = 0; v < 4; v++) acc[i][j][v] = 0.f;

    const int nk = K / 64;

    hfill(A, Bh, K, N, rowBlk, colBlk, 0, asb, bsb, tid);
    asm volatile("cp.async.commit_group;");

    for (int kt = 0; kt < nk; kt++) {
        if (kt + 1 < nk) {
            int s2 = (kt + 1) & 1;
            hfill(A, Bh, K, N, rowBlk, colBlk, kt + 1,
                  asb + s2 * A_STAGE, bsb + s2 * B_STAGE, tid);
            asm volatile("cp.async.commit_group;");
            asm volatile("cp.async.wait_group 1;");
        } else {
            asm volatile("cp.async.wait_group 0;");
        }
        __syncthreads();
        const uint32_t ab = asb + (kt & 1) * A_STAGE;
        const uint32_t bb = bsb + (kt & 1) * B_STAGE;
#pragma unroll
        for (int ks = 0; ks < 64; ks += 16) {
            uint32_t af[4][4], bf[2][4];
#pragma unroll
            for (int mi = 0; mi < 4; mi++) {
                int row = wr * 64 + mi * 16 + r8 + (grp & 1) * 8;
                int kk = ks + (grp >> 1) * 8;
                ldmat_x4(af[mi], ab + row * (GST * 2) + kk * 2);
            }
#pragma unroll
            for (int np = 0; np < 2; np++) {
                int j = ks + r8 + (grp & 1) * 8;
                int d = wc * 32 + np * 16 + (grp >> 1) * 8;
                ldmat_x4t(bf[np], bb + (j * BST + d) * 2);
            }
#pragma unroll
            for (int mi = 0; mi < 4; mi++)
#pragma unroll
                for (int ni = 0; ni < 4; ni++) {
                    uint32_t bq[2] = {bf[ni >> 1][(ni & 1) * 2],
                                      bf[ni >> 1][(ni & 1) * 2 + 1]};
                    mma_f16(acc[mi][ni], af[mi], bq);
                }
        }
        __syncthreads();
    }

#pragma unroll
    for (int mi = 0; mi < 4; mi++) {
#pragma unroll
        for (int ni = 0; ni < 4; ni++) {
            int r0 = rowBlk + wr * 64 + mi * 16 + g;
            int c = colBlk + wc * 32 + ni * 8 + tg * 2;
            float2 bb2 = *(const float2*)(bias + c);
            float2 o0, o1;
            o0.x = acc[mi][ni][0] + bb2.x;
            o0.y = acc[mi][ni][1] + bb2.y;
            o1.x = acc[mi][ni][2] + bb2.x;
            o1.y = acc[mi][ni][3] + bb2.y;
            if (doRelu) {
                o0.x = fmaxf(o0.x, 0.f); o0.y = fmaxf(o0.y, 0.f);
                o1.x = fmaxf(o1.x, 0.f); o1.y = fmaxf(o1.y, 0.f);
            }
            if (res) {
                float2 r0v = *(const float2*)(res + (size_t)r0 * N + c);
                float2 r1v = *(const float2*)(res + (size_t)(r0 + 8) * N + c);
                o0.x += r0v.x; o0.y += r0v.y;
                o1.x += r1v.x; o1.y += r1v.y;
            }
            if (C) {
                *(float2*)(C + (size_t)r0 * N + c) = o0;
                *(float2*)(C + (size_t)(r0 + 8) * N + c) = o1;
            }
            if (Ch) {
                *(__half2*)(Ch + (size_t)r0 * N + c) = __floats2half2_rn(o0.x, o0.y);
                *(__half2*)(Ch + (size_t)(r0 + 8) * N + c) = __floats2half2_rn(o1.x, o1.y);
            }
        }
    }
}

// ---------------- conversions ------------------------------------------------
__global__ __launch_bounds__(256) void f32_to_f16(const float* __restrict__ in,
                                                  __half* __restrict__ out, int n4) {
    int i = blockIdx.x * 256 + threadIdx.x;
    if (i < n4) {
        float4 v = ((const float4*)in)[i];
        ((__half2*)out)[i * 2]     = __floats2half2_rn(v.x, v.y);
        ((__half2*)out)[i * 2 + 1] = __floats2half2_rn(v.z, v.w);
    }
}

__global__ __launch_bounds__(256) void pack_kv_h(const float* __restrict__ Wk,
                                                 const float* __restrict__ Wv,
                                                 __half* __restrict__ out) {
    int i = blockIdx.x * 256 + threadIdx.x;
    if (i >= DMODEL * 2 * DMODEL / 4) return;
    int col4 = i & 511;
    int k = i >> 9;
    const float* src = (col4 < 256) ? (Wk + (size_t)k * DMODEL + col4 * 4)
                                    : (Wv + (size_t)k * DMODEL + (col4 - 256) * 4);
    float4 v = *(const float4*)src;
    __half2* o = (__half2*)(out + (size_t)k * 2 * DMODEL + col4 * 4);
    o[0] = __floats2half2_rn(v.x, v.y);
    o[1] = __floats2half2_rn(v.z, v.w);
}

__global__ void pack_bias2(const float* __restrict__ b0, const float* __restrict__ b1,
                           float* __restrict__ out) {
    int i = blockIdx.x * 256 + threadIdx.x;
    if (i < DMODEL) { out[i] = b0[i]; out[DMODEL + i] = b1[i]; }
}

// ---------------- mask dtype detection + normalization ---------------------
__global__ void detect_mask_stride(const unsigned char* __restrict__ m, int* stride_out) {
    __shared__ int any;
    if (threadIdx.x == 0) any = 0;
    __syncthreads();
    int a = 0;
    for (int j = threadIdx.x; j < 2048; j += 256) a |= m[j * 4 + 1];
    if (a) atomicOr(&any, 1);
    __syncthreads();
    if (threadIdx.x == 0) *stride_out = any ? 1 : 4;
}

__global__ void mask_prep(const unsigned char* __restrict__ m,
                          const int* __restrict__ stridep,
                          unsigned char* __restrict__ em, int* __restrict__ allpad) {
    int b = blockIdx.x;
    int st = *stridep;
    int ok = 1;
    for (int j = threadIdx.x; j < LSEQ; j += 256) {
        unsigned char v = (m[(size_t)(b * LSEQ + j) * st] != 0) ? 1 : 0;
        em[b * LSEQ + j] = v;
        ok &= (int)v;
    }
    ok = __syncthreads_and(ok);
    if (threadIdx.x == 0) allpad[b] = ok;
}

// ---------------- FA2-style fp16 flash attention -----------------------------
#define AST 72
#define KV_BUF (64 * AST)
#define ATT2_SMEM (128 * AST * 2 + 4 * KV_BUF * 2 + 2 * 64 * 4)

__global__ __launch_bounds__(256) void attn_fa(
    const __half* __restrict__ qp, const __half* __restrict__ kp,
    const __half* __restrict__ vp, const unsigned char* __restrict__ em,
    const int* __restrict__ allpad, __half* __restrict__ out, int kvstride) {
    extern __shared__ char smraw[];
    __half* Qs = (__half*)smraw;
    __half* Ks = Qs + 128 * AST;
    __half* Vs = Ks + 2 * KV_BUF;
    float* mk = (float*)(Vs + 2 * KV_BUF);
    const uint32_t sb = (uint32_t)__cvta_generic_to_shared(smraw);
    const uint32_t qsb = sb;
    const uint32_t ksb = sb + 128 * AST * 2;
    const uint32_t vsb = ksb + 2 * KV_BUF * 2;

    const int b = blockIdx.z, h = blockIdx.y, q0 = blockIdx.x * 128;
    const int tid = threadIdx.x;
    const int lane = tid & 31, warp = tid >> 5;
    const int g = lane >> 2, tg = lane & 3;
    const int grp = lane >> 3, r8 = lane & 7;
    const int ap = allpad[b];
    const size_t qoff = ((size_t)(b * LSEQ + q0) * DMODEL) + h * HDIM;

    {
        const size_t koff = ((size_t)(b * LSEQ) * kvstride) + h * HDIM;
        for (int t = tid; t < 512; t += 256) {
            int row = t >> 3, ch = t & 7;
            cpa16(ksb + row * (AST * 2) + ch * 16, kp + koff + (size_t)row * kvstride + ch * 8);
            cpa16(vsb + row * (AST * 2) + ch * 16, vp + koff + (size_t)row * kvstride + ch * 8);
        }
        asm volatile("cp.async.commit_group;");
    }
    for (int t = tid; t < 1024; t += 256) {
        int i = t >> 3, ch = t & 7;
        *(uint4*)&Qs[i * AST + ch * 8] =
            *(const uint4*)(qp + qoff + (size_t)i * DMODEL + ch * 8);
    }
    if (tid < 64) {
        int msk = em[b * LSEQ + tid];
        mk[tid] = msk ? 1.0f : 0.0f;
    }
    __syncthreads();

    uint32_t qf[4][4];
#pragma unroll
    for (int c = 0; c < 4; c++) {
        int row = 16 * warp + r8 + (grp & 1) * 8;
        int kk = 16 * c + (grp >> 1) * 8;
        ldmat_x4(qf[c], qsb + (row * AST + kk) * 2);
    }

    float m0 = -1e30f, m1 = -1e30f, l0 = 0.f, l1 = 0.f;
    float acc[8][4];
#pragma unroll
    for (int i = 0; i < 8; i++)
#pragma unroll
        for (int v = 0; v < 4; v++) acc[i][v] = 0.f;

    for (int kt = 0; kt < 16; kt++) {
        const int cur = kt & 1;
        if (kt + 1 < 16) {
            const int nxt = (kt + 1) & 1;
            const size_t koff = ((size_t)(b * LSEQ + (kt + 1) * 64) * kvstride) + h * HDIM;
            for (int t = tid; t < 512; t += 256) {
                int row = t >> 3, ch = t & 7;
                cpa16(ksb + nxt * KV_BUF * 2 + row * (AST * 2) + ch * 16,
                      kp + koff + (size_t)row * kvstride + ch * 8);
                cpa16(vsb + nxt * KV_BUF * 2 + row * (AST * 2) + ch * 16,
                      vp + koff + (size_t)row * kvstride + ch * 8);
            }
            asm volatile("cp.async.commit_group;");
            asm volatile("cp.async.wait_group 1;");
        } else {
            asm volatile("cp.async.wait_group 0;");
        }
        __syncthreads();
        if (kt + 1 < 16 && tid < 64) {
            int kidx = (kt + 1) * 64 + tid;
            int msk = em[b * LSEQ + kidx];
            if (ap && kidx == LSEQ - 1) msk = 0;
            mk[((kt + 1) & 1) * 64 + tid] = msk ? 1.0f : 0.0f;
        }

        const uint32_t kb = ksb + cur * KV_BUF * 2;
        const uint32_t vb = vsb + cur * KV_BUF * 2;
        const float* mkc = mk + cur * 64;

        float s[8][4];
#pragma unroll
        for (int i = 0; i < 8; i++)
#pragma unroll
            for (int v = 0; v < 4; v++) s[i][v] = 0.f;
#pragma unroll
        for (int c = 0; c < 4; c++) {
#pragma unroll
            for (int ng = 0; ng < 4; ng++) {
                uint32_t bf[4];
                int n = 16 * ng + r8 + (grp >> 1) * 8;
                int kk = 16 * c + (grp & 1) * 8;
                ldmat_x4(bf, kb + (n * AST + kk) * 2);
                uint32_t b0[2] = {bf[0], bf[1]};
                uint32_t b1[2] = {bf[2], bf[3]};
                mma_f16(s[2 * ng], qf[c], b0);
                mma_f16(s[2 * ng + 1], qf[c], b1);
            }
        }

#pragma unroll
        for (int ni = 0; ni < 8; ni++) {
            int c0 = ni * 8 + tg * 2;
            float k0 = mkc[c0], k1 = mkc[c0 + 1];
            s[ni][0] = (k0 != 0.f) ? -10000.f : s[ni][0] * ATT_SCALE;
            s[ni][1] = (k1 != 0.f) ? -10000.f : s[ni][1] * ATT_SCALE;
            s[ni][2] = (k0 != 0.f) ? -10000.f : s[ni][2] * ATT_SCALE;
            s[ni][3] = (k1 != 0.f) ? -10000.f : s[ni][3] * ATT_SCALE;
        }

        float mt0 = -1e30f, mt1 = -1e30f;
#pragma unroll
        for (int ni = 0; ni < 8; ni++) {
            mt0 = fmaxf(mt0, fmaxf(s[ni][0], s[ni][1]));
            mt1 = fmaxf(mt1, fmaxf(s[ni][2], s[ni][3]));
        }
        mt0 = fmaxf(mt0, __shfl_xor_sync(0xffffffffu, mt0, 1));
        mt0 = fmaxf(mt0, __shfl_xor_sync(0xffffffffu, mt0, 2));
        mt1 = fmaxf(mt1, __shfl_xor_sync(0xffffffffu, mt1, 1));
        mt1 = fmaxf(mt1, __shfl_xor_sync(0xffffffffu, mt1, 2));
        float nm0 = fmaxf(m0, mt0), nm1 = fmaxf(m1, mt1);
        float a0 = __expf(m0 - nm0), a1 = __expf(m1 - nm1);

        uint32_t pa[8], pb[8];
        float sum0 = 0.f, sum1 = 0.f;
#pragma unroll
        for (int ni = 0; ni < 8; ni++) {
            __half2 hA = __floats2half2_rn(__expf(s[ni][0] - nm0), __expf(s[ni][1] - nm0));
            __half2 hB = __floats2half2_rn(__expf(s[ni][2] - nm1), __expf(s[ni][3] - nm1));
            pa[ni] = *(uint32_t*)&hA;
            pb[ni] = *(uint32_t*)&hB;
            sum0 += __low2float(hA) + __high2float(hA);
            sum1 += __low2float(hB) + __high2float(hB);
        }
        sum0 += __shfl_xor_sync(0xffffffffu, sum0, 1);
        sum0 += __shfl_xor_sync(0xffffffffu, sum0, 2);
        sum1 += __shfl_xor_sync(0xffffffffu, sum1, 1);
        sum1 += __shfl_xor_sync(0xffffffffu, sum1, 2);
        m0 = nm0; m1 = nm1;
        l0 = l0 * a0 + sum0;
        l1 = l1 * a1 + sum1;
#pragma unroll
        for (int ni = 0; ni < 8; ni++) {
            acc[ni][0] *= a0; acc[ni][1] *= a0;
            acc[ni][2] *= a1; acc[ni][3] *= a1;
        }

#pragma unroll
        for (int c = 0; c < 4; c++) {
            uint32_t af[4] = {pa[2 * c], pb[2 * c], pa[2 * c + 1], pb[2 * c + 1]};
#pragma unroll
            for (int dg = 0; dg < 4; dg++) {
                uint32_t bf[4];
                int j = 16 * c + r8 + (grp & 1) * 8;
                int d = 16 * dg + (grp >> 1) * 8;
                ldmat_x4t(bf, vb + (j * AST + d) * 2);
                uint32_t b0[2] = {bf[0], bf[1]};
                uint32_t b1[2] = {bf[2], bf[3]};
                mma_f16(acc[2 * dg], af, b0);
                mma_f16(acc[2 * dg + 1], af, b1);
            }
        }
        __syncthreads();
    }

    float i0v = 1.0f / l0, i1v = 1.0f / l1;
    int r0 = q0 + 16 * warp + g;
#pragma unroll
    for (int ni = 0; ni < 8; ni++) {
        int cc = h * HDIM + ni * 8 + tg * 2;
        *(__half2*)(out + (size_t)(b * LSEQ + r0) * DMODEL + cc) =
            __floats2half2_rn(acc[ni][0] * i0v, acc[ni][1] * i0v);
        *(__half2*)(out + (size_t)(b * LSEQ + r0 + 8) * DMODEL + cc) =
            __floats2half2_rn(acc[ni][2] * i1v, acc[ni][3] * i1v);
    }
}

// ---------------- LayerNorm (optional half twin output) --------------------
__global__ __launch_bounds__(256) void ln_kernel(
    const float* __restrict__ X, const float* __restrict__ gam,
    const float* __restrict__ bet, float* __restrict__ Y, __half* __restrict__ Yh) {
    __shared__ float red[8];
    __shared__ float sMean, sVar;
    const int row = blockIdx.x;
    const int tid = threadIdx.x;
    const float* x = X + (size_t)row * DMODEL;
    float4 v = *(const float4*)(x + tid * 4);
    float s = v.x + v.y + v.z + v.w;
#pragma unroll
    for (int o = 16; o; o >>= 1) s += __shfl_xor_sync(0xffffffffu, s, o);
    int w = tid >> 5, lane = tid & 31;
    if (lane == 0) red[w] = s;
    __syncthreads();
    if (tid == 0) {
        float t = 0;
#pragma unroll
        for (int i = 0; i < 8; i++) t += red[i];
        sMean = t * (1.0f / DMODEL);
    }
    __syncthreads();
    float m = sMean;
    float dx = v.x - m, dy = v.y - m, dz = v.z - m, dw = v.w - m;
    float q = dx * dx + dy * dy + dz * dz + dw * dw;
#pragma unroll
    for (int o = 16; o; o >>= 1) q += __shfl_xor_sync(0xffffffffu, q, o);
    if (lane == 0) red[w] = q;
    __syncthreads();
    if (tid == 0) {
        float t = 0;
#pragma unroll
        for (int i = 0; i < 8; i++) t += red[i];
        sVar = t * (1.0f / DMODEL);
    }
    __syncthreads();
    float inv = rsqrtf(sVar + LN_EPS);
    float4 gv = *(const float4*)(gam + tid * 4);
    float4 bv = *(const float4*)(bet + tid * 4);
    float4 o;
    o.x = dx * inv * gv.x + bv.x;
    o.y = dy * inv * gv.y + bv.y;
    o.z = dz * inv * gv.z + bv.z;
    o.w = dw * inv * gv.w + bv.w;
    *(float4*)(Y + (size_t)row * DMODEL + tid * 4) = o;
    if (Yh) {
        __half2* yh = (__half2*)(Yh + (size_t)row * DMODEL + tid * 4);
        yh[0] = __floats2half2_rn(o.x, o.y);
        yh[1] = __floats2half2_rn(o.z, o.w);
    }
}

// ---------------- launch ----------------------------------------------------
extern "C" void kernel_launch(void* const* d_in, const int* in_sizes, int n_in,
                              void* d_out, int out_size) {
    const float* q  = (const float*)d_in[0];
    const float* kv = (const float*)d_in[1];
    const unsigned char* kvm = (const unsigned char*)d_in[2];
    const float* Wq = (const float*)d_in[3];
    const float* bq = (const float*)d_in[4];
    const float* Wk = (const float*)d_in[5];
    const float* bk = (const float*)d_in[6];
    const float* Wv = (const float*)d_in[7];
    const float* bv = (const float*)d_in[8];
    const float* Wo = (const float*)d_in[9];
    const float* bo = (const float*)d_in[10];
    const float* ln1g = (const float*)d_in[11];
    const float* ln1b = (const float*)d_in[12];
    const float* W1 = (const float*)d_in[13];
    const float* b1 = (const float*)d_in[14];
    const float* W2 = (const float*)d_in[15];
    const float* b2 = (const float*)d_in[16];
    const float* ln2g = (const float*)d_in[17];
    const float* ln2b = (const float*)d_in[18];
    float* out = (float*)d_out;

    __half *qh, *kvh, *qph, *kvph, *atth, *xh, *hh;
    __half *wqh, *wkvh, *woh, *w1h, *w2h;
    float *y, *x, *bkv;
    int *allpad, *mstride;
    unsigned char* emask;
    cudaGetSymbolAddress((void**)&qh, g_qh);
    cudaGetSymbolAddress((void**)&kvh, g_kvh);
    cudaGetSymbolAddress((void**)&qph, g_qph);
    cudaGetSymbolAddress((void**)&kvph, g_kvph);
    cudaGetSymbolAddress((void**)&atth, g_atth);
    cudaGetSymbolAddress((void**)&xh, g_xh);
    cudaGetSymbolAddress((void**)&hh, g_hh);
    cudaGetSymbolAddress((void**)&wqh, g_wqh);
    cudaGetSymbolAddress((void**)&wkvh, g_wkvh);
    cudaGetSymbolAddress((void**)&woh, g_woh);
    cudaGetSymbolAddress((void**)&w1h, g_w1h);
    cudaGetSymbolAddress((void**)&w2h, g_w2h);
    cudaGetSymbolAddress((void**)&bkv, g_bkv);
    cudaGetSymbolAddress((void**)&y, g_y);
    cudaGetSymbolAddress((void**)&x, g_x);
    cudaGetSymbolAddress((void**)&allpad, g_allpad);
    cudaGetSymbolAddress((void**)&emask, g_emask);
    cudaGetSymbolAddress((void**)&mstride, g_mstride);

    cudaFuncSetAttribute(hgemm, cudaFuncAttributeMaxDynamicSharedMemorySize, HG_SMEM);
    cudaFuncSetAttribute(attn_fa, cudaFuncAttributeMaxDynamicSharedMemorySize, ATT2_SMEM);

    dim3 blk(256);
    const int DD4 = DMODEL * DMODEL / 4;
    const int QR4 = QROWS * DMODEL / 4;

    cudaStream_t side;
    cudaStreamCreateWithFlags(&side, cudaStreamNonBlocking);
    cudaEvent_t evStart, evCommon, evW, evDone1;
    cudaEventCreateWithFlags(&evStart, cudaEventDisableTiming);
    cudaEventCreateWithFlags(&evCommon, cudaEventDisableTiming);
    cudaEventCreateWithFlags(&evW, cudaEventDisableTiming);
    cudaEventCreateWithFlags(&evDone1, cudaEventDisableTiming);

    // fork
    cudaEventRecord(evStart, 0);
    cudaStreamWaitEvent(side, evStart, 0);

    // ---- MAIN (stream 0): common prep needed by all chunks ----
    f32_to_f16<<<(DD4 + 255) / 256, 256>>>(Wq, wqh, DD4);
    pack_kv_h<<<(DMODEL * 2 * DMODEL / 4 + 255) / 256, 256>>>(Wk, Wv, wkvh);
    pack_bias2<<<(DMODEL + 255) / 256, 256>>>(bk, bv, bkv);
    detect_mask_stride<<<1, 256>>>(kvm, mstride);
    mask_prep<<<BATCH, 256>>>(kvm, mstride, emask, allpad);
    cudaEventRecord(evCommon, 0);

    // ---- SIDE: weight conversions for Wo/FFN (hide under early chunks) ----
    f32_to_f16<<<(DD4 + 255) / 256, 256, 0, side>>>(Wo, woh, DD4);
    f32_to_f16<<<(DMODEL * DFF / 4 + 255) / 256, 256, 0, side>>>(W1, w1h, DMODEL * DFF / 4);
    f32_to_f16<<<(DMODEL * DFF / 4 + 255) / 256, 256, 0, side>>>(W2, w2h, DMODEL * DFF / 4);
    cudaEventRecord(evW, side);
    cudaStreamWaitEvent(side, evCommon, 0);
    cudaStreamWaitEvent(0, evW, 0);

    // ======== per-chunk chain: chunk c on stream st ========
#define CHAIN(c, st)                                                              \
    do {                                                                          \
        const size_t r0 = (size_t)(c) * QROWS;                                    \
        f32_to_f16<<<(QR4 + 255) / 256, 256, 0, (st)>>>(                          \
            q + r0 * DMODEL, qh + r0 * DMODEL, QR4);                              \
        f32_to_f16<<<(QR4 + 255) / 256, 256, 0, (st)>>>(                          \
            kv + r0 * DMODEL, kvh + r0 * DMODEL, QR4);                            \
        hgemm<<<dim3(8, QROWS / 128), blk, HG_SMEM, (st)>>>(                      \
            qh + r0 * DMODEL, wqh, bq, nullptr, nullptr, qph + r0 * DMODEL,       \
            QROWS, DMODEL, DMODEL, 0);                                            \
        hgemm<<<dim3(16, QROWS / 128), blk, HG_SMEM, (st)>>>(                     \
            kvh + r0 * DMODEL, wkvh, bkv, nullptr, nullptr,                       \
            kvph + r0 * 2 * DMODEL, QROWS, 2 * DMODEL, DMODEL, 0);                \
        attn_fa<<<dim3(LSEQ / 128, NHEAD, QB), blk, ATT2_SMEM, (st)>>>(           \
            qph + r0 * DMODEL, kvph + r0 * 2 * DMODEL,                            \
            kvph + r0 * 2 * DMODEL + DMODEL, emask + r0, allpad + (c) * QB,       \
            atth + r0 * DMODEL, 2 * DMODEL);                                      \
        hgemm<<<dim3(8, QROWS / 128), blk, HG_SMEM, (st)>>>(                      \
            atth + r0 * DMODEL, woh, bo, q + r0 * DMODEL, y + r0 * DMODEL,        \
            nullptr, QROWS, DMODEL, DMODEL, 0);                                   \
        ln_kernel<<<QROWS, blk, 0, (st)>>>(                                       \
            y + r0 * DMODEL, ln1g, ln1b, x + r0 * DMODEL, xh + r0 * DMODEL);      \
        hgemm<<<dim3(32, QROWS / 128), blk, HG_SMEM, (st)>>>(                     \
            xh + r0 * DMODEL, w1h, b1, nullptr, nullptr, hh + r0 * DFF,           \
            QROWS, DFF, DMODEL, 1);                                               \
        hgemm<<<dim3(8, QROWS / 128), blk, HG_SMEM, (st)>>>(                      \
            hh + r0 * DFF, w2h, b2, x + r0 * DMODEL, y + r0 * DMODEL,             \
            nullptr, QROWS, DMODEL, DFF, 0);                                      \
        ln_kernel<<<QROWS, blk, 0, (st)>>>(                                       \
            y + r0 * DMODEL, ln2g, ln2b, out + r0 * DMODEL, nullptr);             \
    } while (0)

    // chunks 0,2 on main stream; chunks 1,3 on side stream
    CHAIN(0, 0);
    CHAIN(1, side);
    CHAIN(2, 0);
    CHAIN(3, side);

    cudaEventRecord(evDone1, side);
    cudaStreamWaitEvent(0, evDone1, 0);
#undef CHAIN
}

// round 15
// speedup vs baseline: 1.1512x; 1.1512x over previous
#include <cuda_runtime.h>
#include <cuda_fp16.h>
#include <stdint.h>
#include <math.h>

// Problem constants
#define BATCH 8
#define LSEQ 1024
#define DMODEL 1024
#define NHEAD 16
#define HDIM 64
#define DFF 4096
#define MROWS (BATCH * LSEQ)   // 8192
#define ATT_SCALE 0.125f
#define LN_EPS 1e-5f
#define HALF_B (BATCH / 2)
#define HALF_ROWS (HALF_B * LSEQ)   // 4096

// ---------------- scratch (device globals; no allocation allowed) ----------
__device__ __half g_qh[MROWS * DMODEL];
__device__ __half g_kvh[MROWS * DMODEL];
__device__ __half g_qph[MROWS * DMODEL];
__device__ __half g_kvph[(size_t)MROWS * 2 * DMODEL];   // packed [row][K|V]
__device__ __half g_atth[MROWS * DMODEL];
__device__ __half g_xh[MROWS * DMODEL];
__device__ __half g_hh[(size_t)MROWS * DFF];
__device__ __half g_wqh[DMODEL * DMODEL];               // [K][N] half
__device__ __half g_wkvh[DMODEL * 2 * DMODEL];          // [K][2N]: Wk|Wv packed
__device__ __half g_woh[DMODEL * DMODEL];
__device__ __half g_w1h[DMODEL * DFF];
__device__ __half g_w2h[DFF * DMODEL];
__device__ float g_bkv[2 * DMODEL];
__device__ float g_y[MROWS * DMODEL];
__device__ float g_x[MROWS * DMODEL];
__device__ int g_allpad[BATCH];
__device__ unsigned char g_emask[BATCH * LSEQ];
__device__ int g_mstride[1];

// ---------------- helpers ----------------------------------------------------
__device__ __forceinline__ void cpa16(uint32_t s, const void* g) {
    asm volatile("cp.async.cg.shared.global [%0], [%1], 16;\n" :: "r"(s), "l"(g));
}
__device__ __forceinline__ void ldmat_x4(uint32_t* r, uint32_t addr) {
    asm volatile("ldmatrix.sync.aligned.m8n8.x4.shared.b16 {%0,%1,%2,%3}, [%4];"
        : "=r"(r[0]), "=r"(r[1]), "=r"(r[2]), "=r"(r[3]) : "r"(addr));
}
__device__ __forceinline__ void ldmat_x4t(uint32_t* r, uint32_t addr) {
    asm volatile("ldmatrix.sync.aligned.m8n8.x4.trans.shared.b16 {%0,%1,%2,%3}, [%4];"
        : "=r"(r[0]), "=r"(r[1]), "=r"(r[2]), "=r"(r[3]) : "r"(addr));
}
__device__ __forceinline__ void mma_f16(float* c, const uint32_t* a, const uint32_t* b) {
    asm volatile(
        "mma.sync.aligned.m16n8k16.row.col.f32.f16.f16.f32 "
        "{%0,%1,%2,%3}, {%4,%5,%6,%7}, {%8,%9}, {%0,%1,%2,%3};"
        : "+f"(c[0]), "+f"(c[1]), "+f"(c[2]), "+f"(c[3])
        : "r"(a[0]), "r"(a[1]), "r"(a[2]), "r"(a[3]), "r"(b[0]), "r"(b[1]));
}

// ---------------- FP16 tensor-core GEMM (128x128 tile, BK=64, trans-B) ------
#define GST 72
#define BST 136
#define A_STAGE (128 * GST * 2)
#define B_STAGE (64 * BST * 2)
#define HG_SMEM (2 * (A_STAGE + B_STAGE))  // 71680 B

__device__ __forceinline__ void hfill(const __half* __restrict__ A,
                                      const __half* __restrict__ Bh, int K, int N,
                                      int rowBlk, int colBlk, int kt,
                                      uint32_t abase, uint32_t bbase, int tid) {
#pragma unroll
    for (int c = tid; c < 1024; c += 256) {
        int row = c >> 3, ch = c & 7;
        cpa16(abase + row * (GST * 2) + ch * 16,
              A + (size_t)(rowBlk + row) * K + kt * 64 + ch * 8);
    }
#pragma unroll
    for (int c = tid; c < 1024; c += 256) {
        int row = c >> 4, ch = c & 15;
        cpa16(bbase + row * (BST * 2) + ch * 16,
              Bh + (size_t)(kt * 64 + row) * N + colBlk + ch * 8);
    }
}

__global__ __launch_bounds__(256, 2) void hgemm(
    const __half* __restrict__ A, const __half* __restrict__ Bh,
    const float* __restrict__ bias, const float* __restrict__ res,
    float* __restrict__ C, __half* __restrict__ Ch,
    int M, int N, int K, int doRelu) {
    extern __shared__ char smraw[];
    const uint32_t sb = (uint32_t)__cvta_generic_to_shared(smraw);
    const uint32_t asb = sb;
    const uint32_t bsb = sb + 2 * A_STAGE;

    const int tid = threadIdx.x;
    const int lane = tid & 31, warp = tid >> 5;
    const int wr = warp & 1, wc = warp >> 1;
    const int g = lane >> 2, tg = lane & 3;
    const int grp = lane >> 3, r8 = lane & 7;
    const int rowBlk = blockIdx.y * 128, colBlk = blockIdx.x * 128;

    float acc[4][4][4];
#pragma unroll
    for (int i = 0; i < 4; i++)
#pragma unroll
        for (int j = 0; j < 4; j++)
#pragma unroll
            for (int v = 0; v < 4; v++) acc[i][j][v] = 0.f;

    const int nk = K / 64;

    hfill(A, Bh, K, N, rowBlk, colBlk, 0, asb, bsb, tid);
    asm volatile("cp.async.commit_group;");

    for (int kt = 0; kt < nk; kt++) {
        if (kt + 1 < nk) {
            int s2 = (kt + 1) & 1;
            hfill(A, Bh, K, N, rowBlk, colBlk, kt + 1,
                  asb + s2 * A_STAGE, bsb + s2 * B_STAGE, tid);
            asm volatile("cp.async.commit_group;");
            asm volatile("cp.async.wait_group 1;");
        } else {
            asm volatile("cp.async.wait_group 0;");
        }
        __syncthreads();
        const uint32_t ab = asb + (kt & 1) * A_STAGE;
        const uint32_t bb = bsb + (kt & 1) * B_STAGE;
#pragma unroll
        for (int ks = 0; ks < 64; ks += 16) {
            uint32_t af[4][4], bf[2][4];
#pragma unroll
            for (int mi = 0; mi < 4; mi++) {
                int row = wr * 64 + mi * 16 + r8 + (grp & 1) * 8;
                int kk = ks + (grp >> 1) * 8;
                ldmat_x4(af[mi], ab + row * (GST * 2) + kk * 2);
            }
#pragma unroll
            for (int np = 0; np < 2; np++) {
                int j = ks + r8 + (grp & 1) * 8;
                int d = wc * 32 + np * 16 + (grp >> 1) * 8;
                ldmat_x4t(bf[np], bb + (j * BST + d) * 2);
            }
#pragma unroll
            for (int mi = 0; mi < 4; mi++)
#pragma unroll
                for (int ni = 0; ni < 4; ni++) {
                    uint32_t bq[2] = {bf[ni >> 1][(ni & 1) * 2],
                                      bf[ni >> 1][(ni & 1) * 2 + 1]};
                    mma_f16(acc[mi][ni], af[mi], bq);
                }
        }
        __syncthreads();
    }

#pragma unroll
    for (int mi = 0; mi < 4; mi++) {
#pragma unroll
        for (int ni = 0; ni < 4; ni++) {
            int r0 = rowBlk + wr * 64 + mi * 16 + g;
            int c = colBlk + wc * 32 + ni * 8 + tg * 2;
            float2 bb2 = *(const float2*)(bias + c);
            float2 o0, o1;
            o0.x = acc[mi][ni][0] + bb2.x;
            o0.y = acc[mi][ni][1] + bb2.y;
            o1.x = acc[mi][ni][2] + bb2.x;
            o1.y = acc[mi][ni][3] + bb2.y;
            if (doRelu) {
                o0.x = fmaxf(o0.x, 0.f); o0.y = fmaxf(o0.y, 0.f);
                o1.x = fmaxf(o1.x, 0.f); o1.y = fmaxf(o1.y, 0.f);
            }
            if (res) {
                float2 r0v = *(const float2*)(res + (size_t)r0 * N + c);
                float2 r1v = *(const float2*)(res + (size_t)(r0 + 8) * N + c);
                o0.x += r0v.x; o0.y += r0v.y;
                o1.x += r1v.x; o1.y += r1v.y;
            }
            if (C) {
                *(float2*)(C + (size_t)r0 * N + c) = o0;
                *(float2*)(C + (size_t)(r0 + 8) * N + c) = o1;
            }
            if (Ch) {
                *(__half2*)(Ch + (size_t)r0 * N + c) = __floats2half2_rn(o0.x, o0.y);
                *(__half2*)(Ch + (size_t)(r0 + 8) * N + c) = __floats2half2_rn(o1.x, o1.y);
            }
        }
    }
}

// ---------------- conversions ------------------------------------------------
__global__ __launch_bounds__(256) void f32_to_f16(const float* __restrict__ in,
                                                  __half* __restrict__ out, int n4) {
    int i = blockIdx.x * 256 + threadIdx.x;
    if (i < n4) {
        float4 v = ((const float4*)in)[i];
        ((__half2*)out)[i * 2]     = __floats2half2_rn(v.x, v.y);
        ((__half2*)out)[i * 2 + 1] = __floats2half2_rn(v.z, v.w);
    }
}

__global__ __launch_bounds__(256) void pack_kv_h(const float* __restrict__ Wk,
                                                 const float* __restrict__ Wv,
                                                 __half* __restrict__ out) {
    int i = blockIdx.x * 256 + threadIdx.x;
    if (i >= DMODEL * 2 * DMODEL / 4) return;
    int col4 = i & 511;
    int k = i >> 9;
    const float* src = (col4 < 256) ? (Wk + (size_t)k * DMODEL + col4 * 4)
                                    : (Wv + (size_t)k * DMODEL + (col4 - 256) * 4);
    float4 v = *(const float4*)src;
    __half2* o = (__half2*)(out + (size_t)k * 2 * DMODEL + col4 * 4);
    o[0] = __floats2half2_rn(v.x, v.y);
    o[1] = __floats2half2_rn(v.z, v.w);
}

__global__ void pack_bias2(const float* __restrict__ b0, const float* __restrict__ b1,
                           float* __restrict__ out) {
    int i = blockIdx.x * 256 + threadIdx.x;
    if (i < DMODEL) { out[i] = b0[i]; out[DMODEL + i] = b1[i]; }
}

// ---------------- mask dtype detection + normalization ---------------------
__global__ void detect_mask_stride(const unsigned char* __restrict__ m, int* stride_out) {
    __shared__ int any;
    if (threadIdx.x == 0) any = 0;
    __syncthreads();
    int a = 0;
    for (int j = threadIdx.x; j < 2048; j += 256) a |= m[j * 4 + 1];
    if (a) atomicOr(&any, 1);
    __syncthreads();
    if (threadIdx.x == 0) *stride_out = any ? 1 : 4;
}

__global__ void mask_prep(const unsigned char* __restrict__ m,
                          const int* __restrict__ stridep,
                          unsigned char* __restrict__ em, int* __restrict__ allpad) {
    int b = blockIdx.x;
    int st = *stridep;
    int ok = 1;
    for (int j = threadIdx.x; j < LSEQ; j += 256) {
        unsigned char v = (m[(size_t)(b * LSEQ + j) * st] != 0) ? 1 : 0;
        em[b * LSEQ + j] = v;
        ok &= (int)v;
    }
    ok = __syncthreads_and(ok);
    if (threadIdx.x == 0) allpad[b] = ok;
}

// ---------------- FA2-style fp16 flash attention -----------------------------
#define AST 72
#define KV_BUF (64 * AST)
#define ATT2_SMEM (128 * AST * 2 + 4 * KV_BUF * 2 + 2 * 64 * 4)

__global__ __launch_bounds__(256) void attn_fa(
    const __half* __restrict__ qp, const __half* __restrict__ kp,
    const __half* __restrict__ vp, const unsigned char* __restrict__ em,
    const int* __restrict__ allpad, __half* __restrict__ out, int kvstride) {
    extern __shared__ char smraw[];
    __half* Qs = (__half*)smraw;
    __half* Ks = Qs + 128 * AST;
    __half* Vs = Ks + 2 * KV_BUF;
    float* mk = (float*)(Vs + 2 * KV_BUF);
    const uint32_t sb = (uint32_t)__cvta_generic_to_shared(smraw);
    const uint32_t qsb = sb;
    const uint32_t ksb = sb + 128 * AST * 2;
    const uint32_t vsb = ksb + 2 * KV_BUF * 2;

    const int b = blockIdx.z, h = blockIdx.y, q0 = blockIdx.x * 128;
    const int tid = threadIdx.x;
    const int lane = tid & 31, warp = tid >> 5;
    const int g = lane >> 2, tg = lane & 3;
    const int grp = lane >> 3, r8 = lane & 7;
    const int ap = allpad[b];
    const size_t qoff = ((size_t)(b * LSEQ + q0) * DMODEL) + h * HDIM;

    {
        const size_t koff = ((size_t)(b * LSEQ) * kvstride) + h * HDIM;
        for (int t = tid; t < 512; t += 256) {
            int row = t >> 3, ch = t & 7;
            cpa16(ksb + row * (AST * 2) + ch * 16, kp + koff + (size_t)row * kvstride + ch * 8);
            cpa16(vsb + row * (AST * 2) + ch * 16, vp + koff + (size_t)row * kvstride + ch * 8);
        }
        asm volatile("cp.async.commit_group;");
    }
    for (int t = tid; t < 1024; t += 256) {
        int i = t >> 3, ch = t & 7;
        *(uint4*)&Qs[i * AST + ch * 8] =
            *(const uint4*)(qp + qoff + (size_t)i * DMODEL + ch * 8);
    }
    if (tid < 64) {
        int msk = em[b * LSEQ + tid];
        mk[tid] = msk ? 1.0f : 0.0f;
    }
    __syncthreads();

    uint32_t qf[4][4];
#pragma unroll
    for (int c = 0; c < 4; c++) {
        int row = 16 * warp + r8 + (grp & 1) * 8;
        int kk = 16 * c + (grp >> 1) * 8;
        ldmat_x4(qf[c], qsb + (row * AST + kk) * 2);
    }

    float m0 = -1e30f, m1 = -1e30f, l0 = 0.f, l1 = 0.f;
    float acc[8][4];
#pragma unroll
    for (int i = 0; i < 8; i++)
#pragma unroll
        for (int v = 0; v < 4; v++) acc[i][v] = 0.f;

    for (int kt = 0; kt < 16; kt++) {
        const int cur = kt & 1;
        if (kt + 1 < 16) {
            const int nxt = (kt + 1) & 1;
            const size_t koff = ((size_t)(b * LSEQ + (kt + 1) * 64) * kvstride) + h * HDIM;
            for (int t = tid; t < 512; t += 256) {
                int row = t >> 3, ch = t & 7;
                cpa16(ksb + nxt * KV_BUF * 2 + row * (AST * 2) + ch * 16,
                      kp + koff + (size_t)row * kvstride + ch * 8);
                cpa16(vsb + nxt * KV_BUF * 2 + row * (AST * 2) + ch * 16,
                      vp + koff + (size_t)row * kvstride + ch * 8);
            }
            asm volatile("cp.async.commit_group;");
            asm volatile("cp.async.wait_group 1;");
        } else {
            asm volatile("cp.async.wait_group 0;");
        }
        __syncthreads();
        if (kt + 1 < 16 && tid < 64) {
            int kidx = (kt + 1) * 64 + tid;
            int msk = em[b * LSEQ + kidx];
            if (ap && kidx == LSEQ - 1) msk = 0;
            mk[((kt + 1) & 1) * 64 + tid] = msk ? 1.0f : 0.0f;
        }

        const uint32_t kb = ksb + cur * KV_BUF * 2;
        const uint32_t vb = vsb + cur * KV_BUF * 2;
        const float* mkc = mk + cur * 64;

        float s[8][4];
#pragma unroll
        for (int i = 0; i < 8; i++)
#pragma unroll
            for (int v = 0; v < 4; v++) s[i][v] = 0.f;
#pragma unroll
        for (int c = 0; c < 4; c++) {
#pragma unroll
            for (int ng = 0; ng < 4; ng++) {
                uint32_t bf[4];
                int n = 16 * ng + r8 + (grp >> 1) * 8;
                int kk = 16 * c + (grp & 1) * 8;
                ldmat_x4(bf, kb + (n * AST + kk) * 2);
                uint32_t b0[2] = {bf[0], bf[1]};
                uint32_t b1[2] = {bf[2], bf[3]};
                mma_f16(s[2 * ng], qf[c], b0);
                mma_f16(s[2 * ng + 1], qf[c], b1);
            }
        }

#pragma unroll
        for (int ni = 0; ni < 8; ni++) {
            int c0 = ni * 8 + tg * 2;
            float k0 = mkc[c0], k1 = mkc[c0 + 1];
            s[ni][0] = (k0 != 0.f) ? -10000.f : s[ni][0] * ATT_SCALE;
            s[ni][1] = (k1 != 0.f) ? -10000.f : s[ni][1] * ATT_SCALE;
            s[ni][2] = (k0 != 0.f) ? -10000.f : s[ni][2] * ATT_SCALE;
            s[ni][3] = (k1 != 0.f) ? -10000.f : s[ni][3] * ATT_SCALE;
        }

        float mt0 = -1e30f, mt1 = -1e30f;
#pragma unroll
        for (int ni = 0; ni < 8; ni++) {
            mt0 = fmaxf(mt0, fmaxf(s[ni][0], s[ni][1]));
            mt1 = fmaxf(mt1, fmaxf(s[ni][2], s[ni][3]));
        }
        mt0 = fmaxf(mt0, __shfl_xor_sync(0xffffffffu, mt0, 1));
        mt0 = fmaxf(mt0, __shfl_xor_sync(0xffffffffu, mt0, 2));
        mt1 = fmaxf(mt1, __shfl_xor_sync(0xffffffffu, mt1, 1));
        mt1 = fmaxf(mt1, __shfl_xor_sync(0xffffffffu, mt1, 2));
        float nm0 = fmaxf(m0, mt0), nm1 = fmaxf(m1, mt1);
        float a0 = __expf(m0 - nm0), a1 = __expf(m1 - nm1);

        uint32_t pa[8], pb[8];
        float sum0 = 0.f, sum1 = 0.f;
#pragma unroll
        for (int ni = 0; ni < 8; ni++) {
            __half2 hA = __floats2half2_rn(__expf(s[ni][0] - nm0), __expf(s[ni][1] - nm0));
            __half2 hB = __floats2half2_rn(__expf(s[ni][2] - nm1), __expf(s[ni][3] - nm1));
            pa[ni] = *(uint32_t*)&hA;
            pb[ni] = *(uint32_t*)&hB;
            sum0 += __low2float(hA) + __high2float(hA);
            sum1 += __low2float(hB) + __high2float(hB);
        }
        sum0 += __shfl_xor_sync(0xffffffffu, sum0, 1);
        sum0 += __shfl_xor_sync(0xffffffffu, sum0, 2);
        sum1 += __shfl_xor_sync(0xffffffffu, sum1, 1);
        sum1 += __shfl_xor_sync(0xffffffffu, sum1, 2);
        m0 = nm0; m1 = nm1;
        l0 = l0 * a0 + sum0;
        l1 = l1 * a1 + sum1;
#pragma unroll
        for (int ni = 0; ni < 8; ni++) {
            acc[ni][0] *= a0; acc[ni][1] *= a0;
            acc[ni][2] *= a1; acc[ni][3] *= a1;
        }

#pragma unroll
        for (int c = 0; c < 4; c++) {
            uint32_t af[4] = {pa[2 * c], pb[2 * c], pa[2 * c + 1], pb[2 * c + 1]};
#pragma unroll
            for (int dg = 0; dg < 4; dg++) {
                uint32_t bf[4];
                int j = 16 * c + r8 + (grp & 1) * 8;
                int d = 16 * dg + (grp >> 1) * 8;
                ldmat_x4t(bf, vb + (j * AST + d) * 2);
                uint32_t b0[2] = {bf[0], bf[1]};
                uint32_t b1[2] = {bf[2], bf[3]};
                mma_f16(acc[2 * dg], af, b0);
                mma_f16(acc[2 * dg + 1], af, b1);
            }
        }
        __syncthreads();
    }

    float i0v = 1.0f / l0, i1v = 1.0f / l1;
    int r0 = q0 + 16 * warp + g;
#pragma unroll
    for (int ni = 0; ni < 8; ni++) {
        int cc = h * HDIM + ni * 8 + tg * 2;
        *(__half2*)(out + (size_t)(b * LSEQ + r0) * DMODEL + cc) =
            __floats2half2_rn(acc[ni][0] * i0v, acc[ni][1] * i0v);
        *(__half2*)(out + (size_t)(b * LSEQ + r0 + 8) * DMODEL + cc) =
            __floats2half2_rn(acc[ni][2] * i1v, acc[ni][3] * i1v);
    }
}

// ---------------- LayerNorm (optional half twin output) --------------------
__global__ __launch_bounds__(256) void ln_kernel(
    const float* __restrict__ X, const float* __restrict__ gam,
    const float* __restrict__ bet, float* __restrict__ Y, __half* __restrict__ Yh) {
    __shared__ float red[8];
    __shared__ float sMean, sVar;
    const int row = blockIdx.x;
    const int tid = threadIdx.x;
    const float* x = X + (size_t)row * DMODEL;
    float4 v = *(const float4*)(x + tid * 4);
    float s = v.x + v.y + v.z + v.w;
#pragma unroll
    for (int o = 16; o; o >>= 1) s += __shfl_xor_sync(0xffffffffu, s, o);
    int w = tid >> 5, lane = tid & 31;
    if (lane == 0) red[w] = s;
    __syncthreads();
    if (tid == 0) {
        float t = 0;
#pragma unroll
        for (int i = 0; i < 8; i++) t += red[i];
        sMean = t * (1.0f / DMODEL);
    }
    __syncthreads();
    float m = sMean;
    float dx = v.x - m, dy = v.y - m, dz = v.z - m, dw = v.w - m;
    float q = dx * dx + dy * dy + dz * dz + dw * dw;
#pragma unroll
    for (int o = 16; o; o >>= 1) q += __shfl_xor_sync(0xffffffffu, q, o);
    if (lane == 0) red[w] = q;
    __syncthreads();
    if (tid == 0) {
        float t = 0;
#pragma unroll
        for (int i = 0; i < 8; i++) t += red[i];
        sVar = t * (1.0f / DMODEL);
    }
    __syncthreads();
    float inv = rsqrtf(sVar + LN_EPS);
    float4 gv = *(const float4*)(gam + tid * 4);
    float4 bv = *(const float4*)(bet + tid * 4);
    float4 o;
    o.x = dx * inv * gv.x + bv.x;
    o.y = dy * inv * gv.y + bv.y;
    o.z = dz * inv * gv.z + bv.z;
    o.w = dw * inv * gv.w + bv.w;
    *(float4*)(Y + (size_t)row * DMODEL + tid * 4) = o;
    if (Yh) {
        __half2* yh = (__half2*)(Yh + (size_t)row * DMODEL + tid * 4);
        yh[0] = __floats2half2_rn(o.x, o.y);
        yh[1] = __floats2half2_rn(o.z, o.w);
    }
}

// ---------------- launch ----------------------------------------------------
extern "C" void kernel_launch(void* const* d_in, const int* in_sizes, int n_in,
                              void* d_out, int out_size) {
    const float* q  = (const float*)d_in[0];
    const float* kv = (const float*)d_in[1];
    const unsigned char* kvm = (const unsigned char*)d_in[2];
    const float* Wq = (const float*)d_in[3];
    const float* bq = (const float*)d_in[4];
    const float* Wk = (const float*)d_in[5];
    const float* bk = (const float*)d_in[6];
    const float* Wv = (const float*)d_in[7];
    const float* bv = (const float*)d_in[8];
    const float* Wo = (const float*)d_in[9];
    const float* bo = (const float*)d_in[10];
    const float* ln1g = (const float*)d_in[11];
    const float* ln1b = (const float*)d_in[12];
    const float* W1 = (const float*)d_in[13];
    const float* b1 = (const float*)d_in[14];
    const float* W2 = (const float*)d_in[15];
    const float* b2 = (const float*)d_in[16];
    const float* ln2g = (const float*)d_in[17];
    const float* ln2b = (const float*)d_in[18];
    float* out = (float*)d_out;

    __half *qh, *kvh, *qph, *kvph, *atth, *xh, *hh;
    __half *wqh, *wkvh, *woh, *w1h, *w2h;
    float *y, *x, *bkv;
    int *allpad, *mstride;
    unsigned char* emask;
    cudaGetSymbolAddress((void**)&qh, g_qh);
    cudaGetSymbolAddress((void**)&kvh, g_kvh);
    cudaGetSymbolAddress((void**)&qph, g_qph);
    cudaGetSymbolAddress((void**)&kvph, g_kvph);
    cudaGetSymbolAddress((void**)&atth, g_atth);
    cudaGetSymbolAddress((void**)&xh, g_xh);
    cudaGetSymbolAddress((void**)&hh, g_hh);
    cudaGetSymbolAddress((void**)&wqh, g_wqh);
    cudaGetSymbolAddress((void**)&wkvh, g_wkvh);
    cudaGetSymbolAddress((void**)&woh, g_woh);
    cudaGetSymbolAddress((void**)&w1h, g_w1h);
    cudaGetSymbolAddress((void**)&w2h, g_w2h);
    cudaGetSymbolAddress((void**)&bkv, g_bkv);
    cudaGetSymbolAddress((void**)&y, g_y);
    cudaGetSymbolAddress((void**)&x, g_x);
    cudaGetSymbolAddress((void**)&allpad, g_allpad);
    cudaGetSymbolAddress((void**)&emask, g_emask);
    cudaGetSymbolAddress((void**)&mstride, g_mstride);

    cudaFuncSetAttribute(hgemm, cudaFuncAttributeMaxDynamicSharedMemorySize, HG_SMEM);
    cudaFuncSetAttribute(attn_fa, cudaFuncAttributeMaxDynamicSharedMemorySize, ATT2_SMEM);

    dim3 blk(256);
    const int DD4 = DMODEL * DMODEL / 4;
    const int HR4 = HALF_ROWS * DMODEL / 4;

    cudaStream_t side;
    cudaStreamCreateWithFlags(&side, cudaStreamNonBlocking);
    cudaEvent_t evStart, evCommon, evW, evDone1;
    cudaEventCreateWithFlags(&evStart, cudaEventDisableTiming);
    cudaEventCreateWithFlags(&evCommon, cudaEventDisableTiming);
    cudaEventCreateWithFlags(&evW, cudaEventDisableTiming);
    cudaEventCreateWithFlags(&evDone1, cudaEventDisableTiming);

    // fork
    cudaEventRecord(evStart, 0);
    cudaStreamWaitEvent(side, evStart, 0);

    // ---- MAIN (stream 0): common prep needed by both chains ----
    f32_to_f16<<<(DD4 + 255) / 256, 256>>>(Wq, wqh, DD4);
    pack_kv_h<<<(DMODEL * 2 * DMODEL / 4 + 255) / 256, 256>>>(Wk, Wv, wkvh);
    pack_bias2<<<(DMODEL + 255) / 256, 256>>>(bk, bv, bkv);
    detect_mask_stride<<<1, 256>>>(kvm, mstride);
    mask_prep<<<BATCH, 256>>>(kvm, mstride, emask, allpad);
    cudaEventRecord(evCommon, 0);

    // ---- SIDE: weight conversions for Wo/FFN stage (hide under chain0) ----
    f32_to_f16<<<(DD4 + 255) / 256, 256, 0, side>>>(Wo, woh, DD4);
    f32_to_f16<<<(DMODEL * DFF / 4 + 255) / 256, 256, 0, side>>>(W1, w1h, DMODEL * DFF / 4);
    f32_to_f16<<<(DMODEL * DFF / 4 + 255) / 256, 256, 0, side>>>(W2, w2h, DMODEL * DFF / 4);
    cudaEventRecord(evW, side);
    cudaStreamWaitEvent(side, evCommon, 0);

    // ======== chain halves ========
    // PRE: conversions, Q proj, KV proj, attention (no Wo/FFN weights needed)
#define CHAIN_PRE(c, st)                                                          \
    do {                                                                          \
        const size_t r0 = (size_t)(c) * HALF_ROWS;                                \
        f32_to_f16<<<(HR4 + 255) / 256, 256, 0, (st)>>>(                          \
            q + r0 * DMODEL, qh + r0 * DMODEL, HR4);                              \
        f32_to_f16<<<(HR4 + 255) / 256, 256, 0, (st)>>>(                          \
            kv + r0 * DMODEL, kvh + r0 * DMODEL, HR4);                            \
        hgemm<<<dim3(8, HALF_ROWS / 128), blk, HG_SMEM, (st)>>>(                  \
            qh + r0 * DMODEL, wqh, bq, nullptr, nullptr, qph + r0 * DMODEL,       \
            HALF_ROWS, DMODEL, DMODEL, 0);                                        \
        hgemm<<<dim3(16, HALF_ROWS / 128), blk, HG_SMEM, (st)>>>(                 \
            kvh + r0 * DMODEL, wkvh, bkv, nullptr, nullptr,                       \
            kvph + r0 * 2 * DMODEL, HALF_ROWS, 2 * DMODEL, DMODEL, 0);            \
        attn_fa<<<dim3(LSEQ / 128, NHEAD, HALF_B), blk, ATT2_SMEM, (st)>>>(       \
            qph + r0 * DMODEL, kvph + r0 * 2 * DMODEL,                            \
            kvph + r0 * 2 * DMODEL + DMODEL, emask + r0, allpad + (c) * HALF_B,   \
            atth + r0 * DMODEL, 2 * DMODEL);                                      \
    } while (0)

    // POST: Wo proj + residual, LN1, FFN, LN2 (needs woh/w1h/w2h)
#define CHAIN_POST(c, st)                                                         \
    do {                                                                          \
        const size_t r0 = (size_t)(c) * HALF_ROWS;                                \
        hgemm<<<dim3(8, HALF_ROWS / 128), blk, HG_SMEM, (st)>>>(                  \
            atth + r0 * DMODEL, woh, bo, q + r0 * DMODEL, y + r0 * DMODEL,        \
            nullptr, HALF_ROWS, DMODEL, DMODEL, 0);                               \
        ln_kernel<<<HALF_ROWS, blk, 0, (st)>>>(                                   \
            y + r0 * DMODEL, ln1g, ln1b, x + r0 * DMODEL, xh + r0 * DMODEL);      \
        hgemm<<<dim3(32, HALF_ROWS / 128), blk, HG_SMEM, (st)>>>(                 \
            xh + r0 * DMODEL, w1h, b1, nullptr, nullptr, hh + r0 * DFF,           \
            HALF_ROWS, DFF, DMODEL, 1);                                           \
        hgemm<<<dim3(8, HALF_ROWS / 128), blk, HG_SMEM, (st)>>>(                  \
            hh + r0 * DFF, w2h, b2, x + r0 * DMODEL, y + r0 * DMODEL,             \
            nullptr, HALF_ROWS, DMODEL, DFF, 0);                                  \
        ln_kernel<<<HALF_ROWS, blk, 0, (st)>>>(                                   \
            y + r0 * DMODEL, ln2g, ln2b, out + r0 * DMODEL, nullptr);             \
    } while (0)

    // chain0 on main: start immediately after common prep; wait for converted
    // Wo/FFN weights only right before they are first needed.
    CHAIN_PRE(0, 0);
    cudaStreamWaitEvent(0, evW, 0);
    CHAIN_POST(0, 0);

    // chain1 on side: weight convs + evCommon already ordered in-stream.
    CHAIN_PRE(1, side);
    CHAIN_POST(1, side);
    cudaEventRecord(evDone1, side);

    // join
    cudaStreamWaitEvent(0, evDone1, 0);
#undef CHAIN_PRE
#undef CHAIN_POST
}

// round 16
// speedup vs baseline: 1.1552x; 1.0035x over previous
#include <cuda_runtime.h>
#include <cuda_fp16.h>
#include <stdint.h>
#include <math.h>

// Problem constants
#define BATCH 8
#define LSEQ 1024
#define DMODEL 1024
#define NHEAD 16
#define HDIM 64
#define DFF 4096
#define MROWS (BATCH * LSEQ)   // 8192
#define ATT_SCALE 0.125f
#define LN_EPS 1e-5f
#define HALF_B (BATCH / 2)
#define HALF_ROWS (HALF_B * LSEQ)   // 4096

// ---------------- scratch (device globals; no allocation allowed) ----------
__device__ __half g_qh[MROWS * DMODEL];
__device__ __half g_kvh[MROWS * DMODEL];
__device__ __half g_qph[MROWS * DMODEL];
__device__ __half g_kvph[(size_t)MROWS * 2 * DMODEL];   // packed [row][K|V]
__device__ __half g_atth[MROWS * DMODEL];
__device__ __half g_xh[MROWS * DMODEL];                 // LN1 out (half)
__device__ __half g_yh[MROWS * DMODEL];                 // Wo out / FFN2 out (half)
__device__ __half g_hh[(size_t)MROWS * DFF];
__device__ __half g_wqh[DMODEL * DMODEL];               // [K][N] half
__device__ __half g_wkvh[DMODEL * 2 * DMODEL];          // [K][2N]: Wk|Wv packed
__device__ __half g_woh[DMODEL * DMODEL];
__device__ __half g_w1h[DMODEL * DFF];
__device__ __half g_w2h[DFF * DMODEL];
__device__ float g_bkv[2 * DMODEL];
__device__ int g_allpad[BATCH];
__device__ unsigned char g_emask[BATCH * LSEQ];
__device__ int g_mstride[1];

// ---------------- helpers ----------------------------------------------------
__device__ __forceinline__ void cpa16(uint32_t s, const void* g) {
    asm volatile("cp.async.cg.shared.global [%0], [%1], 16;\n" :: "r"(s), "l"(g));
}
__device__ __forceinline__ void ldmat_x4(uint32_t* r, uint32_t addr) {
    asm volatile("ldmatrix.sync.aligned.m8n8.x4.shared.b16 {%0,%1,%2,%3}, [%4];"
        : "=r"(r[0]), "=r"(r[1]), "=r"(r[2]), "=r"(r[3]) : "r"(addr));
}
__device__ __forceinline__ void ldmat_x4t(uint32_t* r, uint32_t addr) {
    asm volatile("ldmatrix.sync.aligned.m8n8.x4.trans.shared.b16 {%0,%1,%2,%3}, [%4];"
        : "=r"(r[0]), "=r"(r[1]), "=r"(r[2]), "=r"(r[3]) : "r"(addr));
}
__device__ __forceinline__ void mma_f16(float* c, const uint32_t* a, const uint32_t* b) {
    asm volatile(
        "mma.sync.aligned.m16n8k16.row.col.f32.f16.f16.f32 "
        "{%0,%1,%2,%3}, {%4,%5,%6,%7}, {%8,%9}, {%0,%1,%2,%3};"
        : "+f"(c[0]), "+f"(c[1]), "+f"(c[2]), "+f"(c[3])
        : "r"(a[0]), "r"(a[1]), "r"(a[2]), "r"(a[3]), "r"(b[0]), "r"(b[1]));
}

// ---------------- FP16 tensor-core GEMM (128x128 tile, BK=64, trans-B) ------
#define GST 72
#define BST 136
#define A_STAGE (128 * GST * 2)
#define B_STAGE (64 * BST * 2)
#define HG_SMEM (2 * (A_STAGE + B_STAGE))  // 71680 B

__device__ __forceinline__ void hfill(const __half* __restrict__ A,
                                      const __half* __restrict__ Bh, int K, int N,
                                      int rowBlk, int colBlk, int kt,
                                      uint32_t abase, uint32_t bbase, int tid) {
#pragma unroll
    for (int c = tid; c < 1024; c += 256) {
        int row = c >> 3, ch = c & 7;
        cpa16(abase + row * (GST * 2) + ch * 16,
              A + (size_t)(rowBlk + row) * K + kt * 64 + ch * 8);
    }
#pragma unroll
    for (int c = tid; c < 1024; c += 256) {
        int row = c >> 4, ch = c & 15;
        cpa16(bbase + row * (BST * 2) + ch * 16,
              Bh + (size_t)(kt * 64 + row) * N + colBlk + ch * 8);
    }
}

__global__ __launch_bounds__(256, 2) void hgemm(
    const __half* __restrict__ A, const __half* __restrict__ Bh,
    const float* __restrict__ bias, const float* __restrict__ res,
    const __half* __restrict__ resh,
    float* __restrict__ C, __half* __restrict__ Ch,
    int M, int N, int K, int doRelu) {
    extern __shared__ char smraw[];
    const uint32_t sb = (uint32_t)__cvta_generic_to_shared(smraw);
    const uint32_t asb = sb;
    const uint32_t bsb = sb + 2 * A_STAGE;

    const int tid = threadIdx.x;
    const int lane = tid & 31, warp = tid >> 5;
    const int wr = warp & 1, wc = warp >> 1;
    const int g = lane >> 2, tg = lane & 3;
    const int grp = lane >> 3, r8 = lane & 7;
    const int rowBlk = blockIdx.y * 128, colBlk = blockIdx.x * 128;

    float acc[4][4][4];
#pragma unroll
    for (int i = 0; i < 4; i++)
#pragma unroll
        for (int j = 0; j < 4; j++)
#pragma unroll
            for (int v = 0; v < 4; v++) acc[i][j][v] = 0.f;

    const int nk = K / 64;

    hfill(A, Bh, K, N, rowBlk, colBlk, 0, asb, bsb, tid);
    asm volatile("cp.async.commit_group;");

    for (int kt = 0; kt < nk; kt++) {
        if (kt + 1 < nk) {
            int s2 = (kt + 1) & 1;
            hfill(A, Bh, K, N, rowBlk, colBlk, kt + 1,
                  asb + s2 * A_STAGE, bsb + s2 * B_STAGE, tid);
            asm volatile("cp.async.commit_group;");
            asm volatile("cp.async.wait_group 1;");
        } else {
            asm volatile("cp.async.wait_group 0;");
        }
        __syncthreads();
        const uint32_t ab = asb + (kt & 1) * A_STAGE;
        const uint32_t bb = bsb + (kt & 1) * B_STAGE;
#pragma unroll
        for (int ks = 0; ks < 64; ks += 16) {
            uint32_t af[4][4], bf[2][4];
#pragma unroll
            for (int mi = 0; mi < 4; mi++) {
                int row = wr * 64 + mi * 16 + r8 + (grp & 1) * 8;
                int kk = ks + (grp >> 1) * 8;
                ldmat_x4(af[mi], ab + row * (GST * 2) + kk * 2);
            }
#pragma unroll
            for (int np = 0; np < 2; np++) {
                int j = ks + r8 + (grp & 1) * 8;
                int d = wc * 32 + np * 16 + (grp >> 1) * 8;
                ldmat_x4t(bf[np], bb + (j * BST + d) * 2);
            }
#pragma unroll
            for (int mi = 0; mi < 4; mi++)
#pragma unroll
                for (int ni = 0; ni < 4; ni++) {
                    uint32_t bq[2] = {bf[ni >> 1][(ni & 1) * 2],
                                      bf[ni >> 1][(ni & 1) * 2 + 1]};
                    mma_f16(acc[mi][ni], af[mi], bq);
                }
        }
        __syncthreads();
    }

#pragma unroll
    for (int mi = 0; mi < 4; mi++) {
#pragma unroll
        for (int ni = 0; ni < 4; ni++) {
            int r0 = rowBlk + wr * 64 + mi * 16 + g;
            int c = colBlk + wc * 32 + ni * 8 + tg * 2;
            float2 bb2 = *(const float2*)(bias + c);
            float2 o0, o1;
            o0.x = acc[mi][ni][0] + bb2.x;
            o0.y = acc[mi][ni][1] + bb2.y;
            o1.x = acc[mi][ni][2] + bb2.x;
            o1.y = acc[mi][ni][3] + bb2.y;
            if (doRelu) {
                o0.x = fmaxf(o0.x, 0.f); o0.y = fmaxf(o0.y, 0.f);
                o1.x = fmaxf(o1.x, 0.f); o1.y = fmaxf(o1.y, 0.f);
            }
            if (res) {
                float2 r0v = *(const float2*)(res + (size_t)r0 * N + c);
                float2 r1v = *(const float2*)(res + (size_t)(r0 + 8) * N + c);
                o0.x += r0v.x; o0.y += r0v.y;
                o1.x += r1v.x; o1.y += r1v.y;
            }
            if (resh) {
                __half2 rh0 = *(const __half2*)(resh + (size_t)r0 * N + c);
                __half2 rh1 = *(const __half2*)(resh + (size_t)(r0 + 8) * N + c);
                o0.x += __low2float(rh0); o0.y += __high2float(rh0);
                o1.x += __low2float(rh1); o1.y += __high2float(rh1);
            }
            if (C) {
                *(float2*)(C + (size_t)r0 * N + c) = o0;
                *(float2*)(C + (size_t)(r0 + 8) * N + c) = o1;
            }
            if (Ch) {
                *(__half2*)(Ch + (size_t)r0 * N + c) = __floats2half2_rn(o0.x, o0.y);
                *(__half2*)(Ch + (size_t)(r0 + 8) * N + c) = __floats2half2_rn(o1.x, o1.y);
            }
        }
    }
}

// ---------------- conversions ------------------------------------------------
__global__ __launch_bounds__(256) void f32_to_f16(const float* __restrict__ in,
                                                  __half* __restrict__ out, int n4) {
    int i = blockIdx.x * 256 + threadIdx.x;
    if (i < n4) {
        float4 v = ((const float4*)in)[i];
        ((__half2*)out)[i * 2]     = __floats2half2_rn(v.x, v.y);
        ((__half2*)out)[i * 2 + 1] = __floats2half2_rn(v.z, v.w);
    }
}

__global__ __launch_bounds__(256) void pack_kv_h(const float* __restrict__ Wk,
                                                 const float* __restrict__ Wv,
                                                 __half* __restrict__ out) {
    int i = blockIdx.x * 256 + threadIdx.x;
    if (i >= DMODEL * 2 * DMODEL / 4) return;
    int col4 = i & 511;
    int k = i >> 9;
    const float* src = (col4 < 256) ? (Wk + (size_t)k * DMODEL + col4 * 4)
                                    : (Wv + (size_t)k * DMODEL + (col4 - 256) * 4);
    float4 v = *(const float4*)src;
    __half2* o = (__half2*)(out + (size_t)k * 2 * DMODEL + col4 * 4);
    o[0] = __floats2half2_rn(v.x, v.y);
    o[1] = __floats2half2_rn(v.z, v.w);
}

__global__ void pack_bias2(const float* __restrict__ b0, const float* __restrict__ b1,
                           float* __restrict__ out) {
    int i = blockIdx.x * 256 + threadIdx.x;
    if (i < DMODEL) { out[i] = b0[i]; out[DMODEL + i] = b1[i]; }
}

// ---------------- mask dtype detection + normalization ---------------------
__global__ void detect_mask_stride(const unsigned char* __restrict__ m, int* stride_out) {
    __shared__ int any;
    if (threadIdx.x == 0) any = 0;
    __syncthreads();
    int a = 0;
    for (int j = threadIdx.x; j < 2048; j += 256) a |= m[j * 4 + 1];
    if (a) atomicOr(&any, 1);
    __syncthreads();
    if (threadIdx.x == 0) *stride_out = any ? 1 : 4;
}

__global__ void mask_prep(const unsigned char* __restrict__ m,
                          const int* __restrict__ stridep,
                          unsigned char* __restrict__ em, int* __restrict__ allpad) {
    int b = blockIdx.x;
    int st = *stridep;
    int ok = 1;
    for (int j = threadIdx.x; j < LSEQ; j += 256) {
        unsigned char v = (m[(size_t)(b * LSEQ + j) * st] != 0) ? 1 : 0;
        em[b * LSEQ + j] = v;
        ok &= (int)v;
    }
    ok = __syncthreads_and(ok);
    if (threadIdx.x == 0) allpad[b] = ok;
}

// ---------------- FA2-style fp16 flash attention -----------------------------
#define AST 72
#define KV_BUF (64 * AST)
#define ATT2_SMEM (128 * AST * 2 + 4 * KV_BUF * 2 + 2 * 64 * 4)

__global__ __launch_bounds__(256) void attn_fa(
    const __half* __restrict__ qp, const __half* __restrict__ kp,
    const __half* __restrict__ vp, const unsigned char* __restrict__ em,
    const int* __restrict__ allpad, __half* __restrict__ out, int kvstride) {
    extern __shared__ char smraw[];
    __half* Qs = (__half*)smraw;
    __half* Ks = Qs + 128 * AST;
    __half* Vs = Ks + 2 * KV_BUF;
    float* mk = (float*)(Vs + 2 * KV_BUF);
    const uint32_t sb = (uint32_t)__cvta_generic_to_shared(smraw);
    const uint32_t qsb = sb;
    const uint32_t ksb = sb + 128 * AST * 2;
    const uint32_t vsb = ksb + 2 * KV_BUF * 2;

    const int b = blockIdx.z, h = blockIdx.y, q0 = blockIdx.x * 128;
    const int tid = threadIdx.x;
    const int lane = tid & 31, warp = tid >> 5;
    const int g = lane >> 2, tg = lane & 3;
    const int grp = lane >> 3, r8 = lane & 7;
    const int ap = allpad[b];
    const size_t qoff = ((size_t)(b * LSEQ + q0) * DMODEL) + h * HDIM;

    {
        const size_t koff = ((size_t)(b * LSEQ) * kvstride) + h * HDIM;
        for (int t = tid; t < 512; t += 256) {
            int row = t >> 3, ch = t & 7;
            cpa16(ksb + row * (AST * 2) + ch * 16, kp + koff + (size_t)row * kvstride + ch * 8);
            cpa16(vsb + row * (AST * 2) + ch * 16, vp + koff + (size_t)row * kvstride + ch * 8);
        }
        asm volatile("cp.async.commit_group;");
    }
    for (int t = tid; t < 1024; t += 256) {
        int i = t >> 3, ch = t & 7;
        *(uint4*)&Qs[i * AST + ch * 8] =
            *(const uint4*)(qp + qoff + (size_t)i * DMODEL + ch * 8);
    }
    if (tid < 64) {
        int msk = em[b * LSEQ + tid];
        mk[tid] = msk ? 1.0f : 0.0f;
    }
    __syncthreads();

    uint32_t qf[4][4];
#pragma unroll
    for (int c = 0; c < 4; c++) {
        int row = 16 * warp + r8 + (grp & 1) * 8;
        int kk = 16 * c + (grp >> 1) * 8;
        ldmat_x4(qf[c], qsb + (row * AST + kk) * 2);
    }

    float m0 = -1e30f, m1 = -1e30f, l0 = 0.f, l1 = 0.f;
    float acc[8][4];
#pragma unroll
    for (int i = 0; i < 8; i++)
#pragma unroll
        for (int v = 0; v < 4; v++) acc[i][v] = 0.f;

    for (int kt = 0; kt < 16; kt++) {
        const int cur = kt & 1;
        if (kt + 1 < 16) {
            const int nxt = (kt + 1) & 1;
            const size_t koff = ((size_t)(b * LSEQ + (kt + 1) * 64) * kvstride) + h * HDIM;
            for (int t = tid; t < 512; t += 256) {
                int row = t >> 3, ch = t & 7;
                cpa16(ksb + nxt * KV_BUF * 2 + row * (AST * 2) + ch * 16,
                      kp + koff + (size_t)row * kvstride + ch * 8);
                cpa16(vsb + nxt * KV_BUF * 2 + row * (AST * 2) + ch * 16,
                      vp + koff + (size_t)row * kvstride + ch * 8);
            }
            asm volatile("cp.async.commit_group;");
            asm volatile("cp.async.wait_group 1;");
        } else {
            asm volatile("cp.async.wait_group 0;");
        }
        __syncthreads();
        if (kt + 1 < 16 && tid < 64) {
            int kidx = (kt + 1) * 64 + tid;
            int msk = em[b * LSEQ + kidx];
            if (ap && kidx == LSEQ - 1) msk = 0;
            mk[((kt + 1) & 1) * 64 + tid] = msk ? 1.0f : 0.0f;
        }

        const uint32_t kb = ksb + cur * KV_BUF * 2;
        const uint32_t vb = vsb + cur * KV_BUF * 2;
        const float* mkc = mk + cur * 64;

        float s[8][4];
#pragma unroll
        for (int i = 0; i < 8; i++)
#pragma unroll
            for (int v = 0; v < 4; v++) s[i][v] = 0.f;
#pragma unroll
        for (int c = 0; c < 4; c++) {
#pragma unroll
            for (int ng = 0; ng < 4; ng++) {
                uint32_t bf[4];
                int n = 16 * ng + r8 + (grp >> 1) * 8;
                int kk = 16 * c + (grp & 1) * 8;
                ldmat_x4(bf, kb + (n * AST + kk) * 2);
                uint32_t b0[2] = {bf[0], bf[1]};
                uint32_t b1[2] = {bf[2], bf[3]};
                mma_f16(s[2 * ng], qf[c], b0);
                mma_f16(s[2 * ng + 1], qf[c], b1);
            }
        }

#pragma unroll
        for (int ni = 0; ni < 8; ni++) {
            int c0 = ni * 8 + tg * 2;
            float k0 = mkc[c0], k1 = mkc[c0 + 1];
            s[ni][0] = (k0 != 0.f) ? -10000.f : s[ni][0] * ATT_SCALE;
            s[ni][1] = (k1 != 0.f) ? -10000.f : s[ni][1] * ATT_SCALE;
            s[ni][2] = (k0 != 0.f) ? -10000.f : s[ni][2] * ATT_SCALE;
            s[ni][3] = (k1 != 0.f) ? -10000.f : s[ni][3] * ATT_SCALE;
        }

        float mt0 = -1e30f, mt1 = -1e30f;
#pragma unroll
        for (int ni = 0; ni < 8; ni++) {
            mt0 = fmaxf(mt0, fmaxf(s[ni][0], s[ni][1]));
            mt1 = fmaxf(mt1, fmaxf(s[ni][2], s[ni][3]));
        }
        mt0 = fmaxf(mt0, __shfl_xor_sync(0xffffffffu, mt0, 1));
        mt0 = fmaxf(mt0, __shfl_xor_sync(0xffffffffu, mt0, 2));
        mt1 = fmaxf(mt1, __shfl_xor_sync(0xffffffffu, mt1, 1));
        mt1 = fmaxf(mt1, __shfl_xor_sync(0xffffffffu, mt1, 2));
        float nm0 = fmaxf(m0, mt0), nm1 = fmaxf(m1, mt1);
        float a0 = __expf(m0 - nm0), a1 = __expf(m1 - nm1);

        uint32_t pa[8], pb[8];
        float sum0 = 0.f, sum1 = 0.f;
#pragma unroll
        for (int ni = 0; ni < 8; ni++) {
            __half2 hA = __floats2half2_rn(__expf(s[ni][0] - nm0), __expf(s[ni][1] - nm0));
            __half2 hB = __floats2half2_rn(__expf(s[ni][2] - nm1), __expf(s[ni][3] - nm1));
            pa[ni] = *(uint32_t*)&hA;
            pb[ni] = *(uint32_t*)&hB;
            sum0 += __low2float(hA) + __high2float(hA);
            sum1 += __low2float(hB) + __high2float(hB);
        }
        sum0 += __shfl_xor_sync(0xffffffffu, sum0, 1);
        sum0 += __shfl_xor_sync(0xffffffffu, sum0, 2);
        sum1 += __shfl_xor_sync(0xffffffffu, sum1, 1);
        sum1 += __shfl_xor_sync(0xffffffffu, sum1, 2);
        m0 = nm0; m1 = nm1;
        l0 = l0 * a0 + sum0;
        l1 = l1 * a1 + sum1;
#pragma unroll
        for (int ni = 0; ni < 8; ni++) {
            acc[ni][0] *= a0; acc[ni][1] *= a0;
            acc[ni][2] *= a1; acc[ni][3] *= a1;
        }

#pragma unroll
        for (int c = 0; c < 4; c++) {
            uint32_t af[4] = {pa[2 * c], pb[2 * c], pa[2 * c + 1], pb[2 * c + 1]};
#pragma unroll
            for (int dg = 0; dg < 4; dg++) {
                uint32_t bf[4];
                int j = 16 * c + r8 + (grp & 1) * 8;
                int d = 16 * dg + (grp >> 1) * 8;
                ldmat_x4t(bf, vb + (j * AST + d) * 2);
                uint32_t b0[2] = {bf[0], bf[1]};
                uint32_t b1[2] = {bf[2], bf[3]};
                mma_f16(acc[2 * dg], af, b0);
                mma_f16(acc[2 * dg + 1], af, b1);
            }
        }
        __syncthreads();
    }

    float i0v = 1.0f / l0, i1v = 1.0f / l1;
    int r0 = q0 + 16 * warp + g;
#pragma unroll
    for (int ni = 0; ni < 8; ni++) {
        int cc = h * HDIM + ni * 8 + tg * 2;
        *(__half2*)(out + (size_t)(b * LSEQ + r0) * DMODEL + cc) =
            __floats2half2_rn(acc[ni][0] * i0v, acc[ni][1] * i0v);
        *(__half2*)(out + (size_t)(b * LSEQ + r0 + 8) * DMODEL + cc) =
            __floats2half2_rn(acc[ni][2] * i1v, acc[ni][3] * i1v);
    }
}

// ---------------- LayerNorm over half input ---------------------------------
// Yh (half) or Yf (float) output; reductions in fp32.
__global__ __launch_bounds__(256) void ln_h(
    const __half* __restrict__ X, const float* __restrict__ gam,
    const float* __restrict__ bet, __half* __restrict__ Yh, float* __restrict__ Yf) {
    __shared__ float red[8];
    __shared__ float sMean, sVar;
    const int row = blockIdx.x;
    const int tid = threadIdx.x;
    const __half2* x2 = (const __half2*)(X + (size_t)row * DMODEL);
    __half2 h0 = x2[tid * 2];
    __half2 h1 = x2[tid * 2 + 1];
    float vx = __low2float(h0), vy = __high2float(h0);
    float vz = __low2float(h1), vw = __high2float(h1);
    float s = vx + vy + vz + vw;
#pragma unroll
    for (int o = 16; o; o >>= 1) s += __shfl_xor_sync(0xffffffffu, s, o);
    int w = tid >> 5, lane = tid & 31;
    if (lane == 0) red[w] = s;
    __syncthreads();
    if (tid == 0) {
        float t = 0;
#pragma unroll
        for (int i = 0; i < 8; i++) t += red[i];
        sMean = t * (1.0f / DMODEL);
    }
    __syncthreads();
    float m = sMean;
    float dx = vx - m, dy = vy - m, dz = vz - m, dw = vw - m;
    float qv = dx * dx + dy * dy + dz * dz + dw * dw;
#pragma unroll
    for (int o = 16; o; o >>= 1) qv += __shfl_xor_sync(0xffffffffu, qv, o);
    if (lane == 0) red[w] = qv;
    __syncthreads();
    if (tid == 0) {
        float t = 0;
#pragma unroll
        for (int i = 0; i < 8; i++) t += red[i];
        sVar = t * (1.0f / DMODEL);
    }
    __syncthreads();
    float inv = rsqrtf(sVar + LN_EPS);
    float4 gv = *(const float4*)(gam + tid * 4);
    float4 bv = *(const float4*)(bet + tid * 4);
    float ox = dx * inv * gv.x + bv.x;
    float oy = dy * inv * gv.y + bv.y;
    float oz = dz * inv * gv.z + bv.z;
    float ow = dw * inv * gv.w + bv.w;
    if (Yh) {
        __half2* yh = (__half2*)(Yh + (size_t)row * DMODEL + tid * 4);
        yh[0] = __floats2half2_rn(ox, oy);
        yh[1] = __floats2half2_rn(oz, ow);
    }
    if (Yf) {
        *(float4*)(Yf + (size_t)row * DMODEL + tid * 4) = make_float4(ox, oy, oz, ow);
    }
}

// ---------------- launch ----------------------------------------------------
extern "C" void kernel_launch(void* const* d_in, const int* in_sizes, int n_in,
                              void* d_out, int out_size) {
    const float* q  = (const float*)d_in[0];
    const float* kv = (const float*)d_in[1];
    const unsigned char* kvm = (const unsigned char*)d_in[2];
    const float* Wq = (const float*)d_in[3];
    const float* bq = (const float*)d_in[4];
    const float* Wk = (const float*)d_in[5];
    const float* bk = (const float*)d_in[6];
    const float* Wv = (const float*)d_in[7];
    const float* bv = (const float*)d_in[8];
    const float* Wo = (const float*)d_in[9];
    const float* bo = (const float*)d_in[10];
    const float* ln1g = (const float*)d_in[11];
    const float* ln1b = (const float*)d_in[12];
    const float* W1 = (const float*)d_in[13];
    const float* b1 = (const float*)d_in[14];
    const float* W2 = (const float*)d_in[15];
    const float* b2 = (const float*)d_in[16];
    const float* ln2g = (const float*)d_in[17];
    const float* ln2b = (const float*)d_in[18];
    float* out = (float*)d_out;

    __half *qh, *kvh, *qph, *kvph, *atth, *xh, *yh, *hh;
    __half *wqh, *wkvh, *woh, *w1h, *w2h;
    float *bkv;
    int *allpad, *mstride;
    unsigned char* emask;
    cudaGetSymbolAddress((void**)&qh, g_qh);
    cudaGetSymbolAddress((void**)&kvh, g_kvh);
    cudaGetSymbolAddress((void**)&qph, g_qph);
    cudaGetSymbolAddress((void**)&kvph, g_kvph);
    cudaGetSymbolAddress((void**)&atth, g_atth);
    cudaGetSymbolAddress((void**)&xh, g_xh);
    cudaGetSymbolAddress((void**)&yh, g_yh);
    cudaGetSymbolAddress((void**)&hh, g_hh);
    cudaGetSymbolAddress((void**)&wqh, g_wqh);
    cudaGetSymbolAddress((void**)&wkvh, g_wkvh);
    cudaGetSymbolAddress((void**)&woh, g_woh);
    cudaGetSymbolAddress((void**)&w1h, g_w1h);
    cudaGetSymbolAddress((void**)&w2h, g_w2h);
    cudaGetSymbolAddress((void**)&bkv, g_bkv);
    cudaGetSymbolAddress((void**)&allpad, g_allpad);
    cudaGetSymbolAddress((void**)&emask, g_emask);
    cudaGetSymbolAddress((void**)&mstride, g_mstride);

    cudaFuncSetAttribute(hgemm, cudaFuncAttributeMaxDynamicSharedMemorySize, HG_SMEM);
    cudaFuncSetAttribute(attn_fa, cudaFuncAttributeMaxDynamicSharedMemorySize, ATT2_SMEM);

    dim3 blk(256);
    const int DD4 = DMODEL * DMODEL / 4;
    const int HR4 = HALF_ROWS * DMODEL / 4;

    cudaStream_t side;
    cudaStreamCreateWithFlags(&side, cudaStreamNonBlocking);
    cudaEvent_t evStart, evCommon, evW, evDone1;
    cudaEventCreateWithFlags(&evStart, cudaEventDisableTiming);
    cudaEventCreateWithFlags(&evCommon, cudaEventDisableTiming);
    cudaEventCreateWithFlags(&evW, cudaEventDisableTiming);
    cudaEventCreateWithFlags(&evDone1, cudaEventDisableTiming);

    // fork
    cudaEventRecord(evStart, 0);
    cudaStreamWaitEvent(side, evStart, 0);

    // ---- MAIN (stream 0): common prep needed by both chains ----
    f32_to_f16<<<(DD4 + 255) / 256, 256>>>(Wq, wqh, DD4);
    pack_kv_h<<<(DMODEL * 2 * DMODEL / 4 + 255) / 256, 256>>>(Wk, Wv, wkvh);
    pack_bias2<<<(DMODEL + 255) / 256, 256>>>(bk, bv, bkv);
    detect_mask_stride<<<1, 256>>>(kvm, mstride);
    mask_prep<<<BATCH, 256>>>(kvm, mstride, emask, allpad);
    cudaEventRecord(evCommon, 0);

    // ---- SIDE: weight conversions for Wo/FFN stage (hide under chain0) ----
    f32_to_f16<<<(DD4 + 255) / 256, 256, 0, side>>>(Wo, woh, DD4);
    f32_to_f16<<<(DMODEL * DFF / 4 + 255) / 256, 256, 0, side>>>(W1, w1h, DMODEL * DFF / 4);
    f32_to_f16<<<(DMODEL * DFF / 4 + 255) / 256, 256, 0, side>>>(W2, w2h, DMODEL * DFF / 4);
    cudaEventRecord(evW, side);
    cudaStreamWaitEvent(side, evCommon, 0);

    // ======== chain halves ========
    // PRE: conversions, Q proj, KV proj, attention (no Wo/FFN weights needed)
#define CHAIN_PRE(c, st)                                                          \
    do {                                                                          \
        const size_t r0 = (size_t)(c) * HALF_ROWS;                                \
        f32_to_f16<<<(HR4 + 255) / 256, 256, 0, (st)>>>(                          \
            q + r0 * DMODEL, qh + r0 * DMODEL, HR4);                              \
        f32_to_f16<<<(HR4 + 255) / 256, 256, 0, (st)>>>(                          \
            kv + r0 * DMODEL, kvh + r0 * DMODEL, HR4);                            \
        hgemm<<<dim3(8, HALF_ROWS / 128), blk, HG_SMEM, (st)>>>(                  \
            qh + r0 * DMODEL, wqh, bq, nullptr, nullptr, nullptr,                 \
            qph + r0 * DMODEL, HALF_ROWS, DMODEL, DMODEL, 0);                     \
        hgemm<<<dim3(16, HALF_ROWS / 128), blk, HG_SMEM, (st)>>>(                 \
            kvh + r0 * DMODEL, wkvh, bkv, nullptr, nullptr, nullptr,              \
            kvph + r0 * 2 * DMODEL, HALF_ROWS, 2 * DMODEL, DMODEL, 0);            \
        attn_fa<<<dim3(LSEQ / 128, NHEAD, HALF_B), blk, ATT2_SMEM, (st)>>>(       \
            qph + r0 * DMODEL, kvph + r0 * 2 * DMODEL,                            \
            kvph + r0 * 2 * DMODEL + DMODEL, emask + r0, allpad + (c) * HALF_B,   \
            atth + r0 * DMODEL, 2 * DMODEL);                                      \
    } while (0)

    // POST: Wo proj + residual(q fp32) -> yh (half); LN1 -> xh (half);
    //       FFN1 -> hh; FFN2 + residual(xh half) -> yh; LN2 -> out (fp32)
#define CHAIN_POST(c, st)                                                         \
    do {                                                                          \
        const size_t r0 = (size_t)(c) * HALF_ROWS;                                \
        hgemm<<<dim3(8, HALF_ROWS / 128), blk, HG_SMEM, (st)>>>(                  \
            atth + r0 * DMODEL, woh, bo, q + r0 * DMODEL, nullptr, nullptr,       \
            yh + r0 * DMODEL, HALF_ROWS, DMODEL, DMODEL, 0);                      \
        ln_h<<<HALF_ROWS, blk, 0, (st)>>>(                                        \
            yh + r0 * DMODEL, ln1g, ln1b, xh + r0 * DMODEL, nullptr);             \
        hgemm<<<dim3(32, HALF_ROWS / 128), blk, HG_SMEM, (st)>>>(                 \
            xh + r0 * DMODEL, w1h, b1, nullptr, nullptr, nullptr,                 \
            hh + r0 * DFF, HALF_ROWS, DFF, DMODEL, 1);                            \
        hgemm<<<dim3(8, HALF_ROWS / 128), blk, HG_SMEM, (st)>>>(                  \
            hh + r0 * DFF, w2h, b2, nullptr, xh + r0 * DMODEL, nullptr,           \
            yh + r0 * DMODEL, HALF_ROWS, DMODEL, DFF, 0);                         \
        ln_h<<<HALF_ROWS, blk, 0, (st)>>>(                                        \
            yh + r0 * DMODEL, ln2g, ln2b, nullptr, out + r0 * DMODEL);            \
    } while (0)

    // chain0 on main: start immediately; wait for Wo/FFN weights only at POST.
    CHAIN_PRE(0, 0);
    cudaStreamWaitEvent(0, evW, 0);
    CHAIN_POST(0, 0);

    // chain1 on side: weight convs + evCommon already ordered in-stream.
    CHAIN_PRE(1, side);
    CHAIN_POST(1, side);
    cudaEventRecord(evDone1, side);

    // join
    cudaStreamWaitEvent(0, evDone1, 0);
#undef CHAIN_PRE
#undef CHAIN_POST
}

// round 17
// speedup vs baseline: 1.1637x; 1.0074x over previous
#include <cuda_runtime.h>
#include <cuda_fp16.h>
#include <stdint.h>
#include <math.h>

// Problem constants
#define BATCH 8
#define LSEQ 1024
#define DMODEL 1024
#define NHEAD 16
#define HDIM 64
#define DFF 4096
#define MROWS (BATCH * LSEQ)   // 8192
#define ATT_SCALE 0.125f
#define LN_EPS 1e-5f
#define HALF_B (BATCH / 2)
#define HALF_ROWS (HALF_B * LSEQ)   // 4096

// ---------------- scratch (device globals; no allocation allowed) ----------
__device__ __half g_qh[MROWS * DMODEL];
__device__ __half g_kvh[MROWS * DMODEL];
__device__ __half g_qph[MROWS * DMODEL];
__device__ __half g_kvph[(size_t)MROWS * 2 * DMODEL];   // packed [row][K|V]
__device__ __half g_atth[MROWS * DMODEL];
__device__ __half g_xh[MROWS * DMODEL];                 // LN1 out (half)
__device__ __half g_yh[MROWS * DMODEL];                 // Wo out / FFN2 out (half)
__device__ __half g_hh[(size_t)MROWS * DFF];
__device__ __half g_wqh[DMODEL * DMODEL];               // [K][N] half
__device__ __half g_wkvh[DMODEL * 2 * DMODEL];          // [K][2N]: Wk|Wv packed
__device__ __half g_woh[DMODEL * DMODEL];
__device__ __half g_w1h[DMODEL * DFF];
__device__ __half g_w2h[DFF * DMODEL];
__device__ float g_bkv[2 * DMODEL];
__device__ int g_allpad[BATCH];
__device__ unsigned char g_emask[BATCH * LSEQ];
__device__ int g_mstride[1];

// ---------------- helpers ----------------------------------------------------
__device__ __forceinline__ void cpa16(uint32_t s, const void* g) {
    asm volatile("cp.async.cg.shared.global [%0], [%1], 16;\n" :: "r"(s), "l"(g));
}
__device__ __forceinline__ void ldmat_x4(uint32_t* r, uint32_t addr) {
    asm volatile("ldmatrix.sync.aligned.m8n8.x4.shared.b16 {%0,%1,%2,%3}, [%4];"
        : "=r"(r[0]), "=r"(r[1]), "=r"(r[2]), "=r"(r[3]) : "r"(addr));
}
__device__ __forceinline__ void ldmat_x4t(uint32_t* r, uint32_t addr) {
    asm volatile("ldmatrix.sync.aligned.m8n8.x4.trans.shared.b16 {%0,%1,%2,%3}, [%4];"
        : "=r"(r[0]), "=r"(r[1]), "=r"(r[2]), "=r"(r[3]) : "r"(addr));
}
__device__ __forceinline__ void mma_f16(float* c, const uint32_t* a, const uint32_t* b) {
    asm volatile(
        "mma.sync.aligned.m16n8k16.row.col.f32.f16.f16.f32 "
        "{%0,%1,%2,%3}, {%4,%5,%6,%7}, {%8,%9}, {%0,%1,%2,%3};"
        : "+f"(c[0]), "+f"(c[1]), "+f"(c[2]), "+f"(c[3])
        : "r"(a[0]), "r"(a[1]), "r"(a[2]), "r"(a[3]), "r"(b[0]), "r"(b[1]));
}

// ---------------- FP16 tensor-core GEMM (128x128 tile, BK=64, trans-B) ------
#define GST 72
#define BST 136
#define A_STAGE (128 * GST * 2)
#define B_STAGE (64 * BST * 2)
#define HG_SMEM (2 * (A_STAGE + B_STAGE))  // 71680 B

__device__ __forceinline__ void hfill(const __half* __restrict__ A,
                                      const __half* __restrict__ Bh, int K, int N,
                                      int rowBlk, int colBlk, int kt,
                                      uint32_t abase, uint32_t bbase, int tid) {
#pragma unroll
    for (int c = tid; c < 1024; c += 256) {
        int row = c >> 3, ch = c & 7;
        cpa16(abase + row * (GST * 2) + ch * 16,
              A + (size_t)(rowBlk + row) * K + kt * 64 + ch * 8);
    }
#pragma unroll
    for (int c = tid; c < 1024; c += 256) {
        int row = c >> 4, ch = c & 15;
        cpa16(bbase + row * (BST * 2) + ch * 16,
              Bh + (size_t)(kt * 64 + row) * N + colBlk + ch * 8);
    }
}

__global__ __launch_bounds__(256, 2) void hgemm(
    const __half* __restrict__ A, const __half* __restrict__ Bh,
    const float* __restrict__ bias, const float* __restrict__ res,
    const __half* __restrict__ resh,
    float* __restrict__ C, __half* __restrict__ Ch,
    int M, int N, int K, int doRelu) {
    extern __shared__ char smraw[];
    const uint32_t sb = (uint32_t)__cvta_generic_to_shared(smraw);
    const uint32_t asb = sb;
    const uint32_t bsb = sb + 2 * A_STAGE;

    const int tid = threadIdx.x;
    const int lane = tid & 31, warp = tid >> 5;
    const int wr = warp & 1, wc = warp >> 1;
    const int g = lane >> 2, tg = lane & 3;
    const int grp = lane >> 3, r8 = lane & 7;
    const int rowBlk = blockIdx.y * 128, colBlk = blockIdx.x * 128;

    float acc[4][4][4];
#pragma unroll
    for (int i = 0; i < 4; i++)
#pragma unroll
        for (int j = 0; j < 4; j++)
#pragma unroll
            for (int v = 0; v < 4; v++) acc[i][j][v] = 0.f;

    const int nk = K / 64;

    hfill(A, Bh, K, N, rowBlk, colBlk, 0, asb, bsb, tid);
    asm volatile("cp.async.commit_group;");

    for (int kt = 0; kt < nk; kt++) {
        if (kt + 1 < nk) {
            int s2 = (kt + 1) & 1;
            hfill(A, Bh, K, N, rowBlk, colBlk, kt + 1,
                  asb + s2 * A_STAGE, bsb + s2 * B_STAGE, tid);
            asm volatile("cp.async.commit_group;");
            asm volatile("cp.async.wait_group 1;");
        } else {
            asm volatile("cp.async.wait_group 0;");
        }
        __syncthreads();
        const uint32_t ab = asb + (kt & 1) * A_STAGE;
        const uint32_t bb = bsb + (kt & 1) * B_STAGE;
#pragma unroll
        for (int ks = 0; ks < 64; ks += 16) {
            uint32_t af[4][4], bf[2][4];
#pragma unroll
            for (int mi = 0; mi < 4; mi++) {
                int row = wr * 64 + mi * 16 + r8 + (grp & 1) * 8;
                int kk = ks + (grp >> 1) * 8;
                ldmat_x4(af[mi], ab + row * (GST * 2) + kk * 2);
            }
#pragma unroll
            for (int np = 0; np < 2; np++) {
                int j = ks + r8 + (grp & 1) * 8;
                int d = wc * 32 + np * 16 + (grp >> 1) * 8;
                ldmat_x4t(bf[np], bb + (j * BST + d) * 2);
            }
#pragma unroll
            for (int mi = 0; mi < 4; mi++)
#pragma unroll
                for (int ni = 0; ni < 4; ni++) {
                    uint32_t bq[2] = {bf[ni >> 1][(ni & 1) * 2],
                                      bf[ni >> 1][(ni & 1) * 2 + 1]};
                    mma_f16(acc[mi][ni], af[mi], bq);
                }
        }
        __syncthreads();
    }

#pragma unroll
    for (int mi = 0; mi < 4; mi++) {
#pragma unroll
        for (int ni = 0; ni < 4; ni++) {
            int r0 = rowBlk + wr * 64 + mi * 16 + g;
            int c = colBlk + wc * 32 + ni * 8 + tg * 2;
            float2 bb2 = *(const float2*)(bias + c);
            float2 o0, o1;
            o0.x = acc[mi][ni][0] + bb2.x;
            o0.y = acc[mi][ni][1] + bb2.y;
            o1.x = acc[mi][ni][2] + bb2.x;
            o1.y = acc[mi][ni][3] + bb2.y;
            if (doRelu) {
                o0.x = fmaxf(o0.x, 0.f); o0.y = fmaxf(o0.y, 0.f);
                o1.x = fmaxf(o1.x, 0.f); o1.y = fmaxf(o1.y, 0.f);
            }
            if (res) {
                float2 r0v = *(const float2*)(res + (size_t)r0 * N + c);
                float2 r1v = *(const float2*)(res + (size_t)(r0 + 8) * N + c);
                o0.x += r0v.x; o0.y += r0v.y;
                o1.x += r1v.x; o1.y += r1v.y;
            }
            if (resh) {
                __half2 rh0 = *(const __half2*)(resh + (size_t)r0 * N + c);
                __half2 rh1 = *(const __half2*)(resh + (size_t)(r0 + 8) * N + c);
                o0.x += __low2float(rh0); o0.y += __high2float(rh0);
                o1.x += __low2float(rh1); o1.y += __high2float(rh1);
            }
            if (C) {
                *(float2*)(C + (size_t)r0 * N + c) = o0;
                *(float2*)(C + (size_t)(r0 + 8) * N + c) = o1;
            }
            if (Ch) {
                *(__half2*)(Ch + (size_t)r0 * N + c) = __floats2half2_rn(o0.x, o0.y);
                *(__half2*)(Ch + (size_t)(r0 + 8) * N + c) = __floats2half2_rn(o1.x, o1.y);
            }
        }
    }
}

// ---------------- conversions ------------------------------------------------
__global__ __launch_bounds__(256) void f32_to_f16(const float* __restrict__ in,
                                                  __half* __restrict__ out, int n4) {
    int i = blockIdx.x * 256 + threadIdx.x;
    if (i < n4) {
        float4 v = ((const float4*)in)[i];
        ((__half2*)out)[i * 2]     = __floats2half2_rn(v.x, v.y);
        ((__half2*)out)[i * 2 + 1] = __floats2half2_rn(v.z, v.w);
    }
}

__global__ __launch_bounds__(256) void pack_kv_h(const float* __restrict__ Wk,
                                                 const float* __restrict__ Wv,
                                                 __half* __restrict__ out) {
    int i = blockIdx.x * 256 + threadIdx.x;
    if (i >= DMODEL * 2 * DMODEL / 4) return;
    int col4 = i & 511;
    int k = i >> 9;
    const float* src = (col4 < 256) ? (Wk + (size_t)k * DMODEL + col4 * 4)
                                    : (Wv + (size_t)k * DMODEL + (col4 - 256) * 4);
    float4 v = *(const float4*)src;
    __half2* o = (__half2*)(out + (size_t)k * 2 * DMODEL + col4 * 4);
    o[0] = __floats2half2_rn(v.x, v.y);
    o[1] = __floats2half2_rn(v.z, v.w);
}

__global__ void pack_bias2(const float* __restrict__ b0, const float* __restrict__ b1,
                           float* __restrict__ out) {
    int i = blockIdx.x * 256 + threadIdx.x;
    if (i < DMODEL) { out[i] = b0[i]; out[DMODEL + i] = b1[i]; }
}

// ---------------- mask dtype detection + normalization ---------------------
__global__ void detect_mask_stride(const unsigned char* __restrict__ m, int* stride_out) {
    __shared__ int any;
    if (threadIdx.x == 0) any = 0;
    __syncthreads();
    int a = 0;
    for (int j = threadIdx.x; j < 2048; j += 256) a |= m[j * 4 + 1];
    if (a) atomicOr(&any, 1);
    __syncthreads();
    if (threadIdx.x == 0) *stride_out = any ? 1 : 4;
}

__global__ void mask_prep(const unsigned char* __restrict__ m,
                          const int* __restrict__ stridep,
                          unsigned char* __restrict__ em, int* __restrict__ allpad) {
    int b = blockIdx.x;
    int st = *stridep;
    int ok = 1;
    for (int j = threadIdx.x; j < LSEQ; j += 256) {
        unsigned char v = (m[(size_t)(b * LSEQ + j) * st] != 0) ? 1 : 0;
        em[b * LSEQ + j] = v;
        ok &= (int)v;
    }
    ok = __syncthreads_and(ok);
    if (threadIdx.x == 0) allpad[b] = ok;
}

// ---------------- FA2-style fp16 flash attention -----------------------------
#define AST 72
#define KV_BUF (64 * AST)
#define ATT2_SMEM (128 * AST * 2 + 4 * KV_BUF * 2 + 2 * 64 * 4)

__global__ __launch_bounds__(256) void attn_fa(
    const __half* __restrict__ qp, const __half* __restrict__ kp,
    const __half* __restrict__ vp, const unsigned char* __restrict__ em,
    const int* __restrict__ allpad, __half* __restrict__ out, int kvstride) {
    extern __shared__ char smraw[];
    __half* Qs = (__half*)smraw;
    __half* Ks = Qs + 128 * AST;
    __half* Vs = Ks + 2 * KV_BUF;
    float* mk = (float*)(Vs + 2 * KV_BUF);
    const uint32_t sb = (uint32_t)__cvta_generic_to_shared(smraw);
    const uint32_t qsb = sb;
    const uint32_t ksb = sb + 128 * AST * 2;
    const uint32_t vsb = ksb + 2 * KV_BUF * 2;

    const int b = blockIdx.z, h = blockIdx.y, q0 = blockIdx.x * 128;
    const int tid = threadIdx.x;
    const int lane = tid & 31, warp = tid >> 5;
    const int g = lane >> 2, tg = lane & 3;
    const int grp = lane >> 3, r8 = lane & 7;
    const int ap = allpad[b];
    const size_t qoff = ((size_t)(b * LSEQ + q0) * DMODEL) + h * HDIM;

    {
        const size_t koff = ((size_t)(b * LSEQ) * kvstride) + h * HDIM;
        for (int t = tid; t < 512; t += 256) {
            int row = t >> 3, ch = t & 7;
            cpa16(ksb + row * (AST * 2) + ch * 16, kp + koff + (size_t)row * kvstride + ch * 8);
            cpa16(vsb + row * (AST * 2) + ch * 16, vp + koff + (size_t)row * kvstride + ch * 8);
        }
        asm volatile("cp.async.commit_group;");
    }
    for (int t = tid; t < 1024; t += 256) {
        int i = t >> 3, ch = t & 7;
        *(uint4*)&Qs[i * AST + ch * 8] =
            *(const uint4*)(qp + qoff + (size_t)i * DMODEL + ch * 8);
    }
    if (tid < 64) {
        int msk = em[b * LSEQ + tid];
        mk[tid] = msk ? 1.0f : 0.0f;
    }
    __syncthreads();

    uint32_t qf[4][4];
#pragma unroll
    for (int c = 0; c < 4; c++) {
        int row = 16 * warp + r8 + (grp & 1) * 8;
        int kk = 16 * c + (grp >> 1) * 8;
        ldmat_x4(qf[c], qsb + (row * AST + kk) * 2);
    }

    float m0 = -1e30f, m1 = -1e30f, l0 = 0.f, l1 = 0.f;
    float acc[8][4];
#pragma unroll
    for (int i = 0; i < 8; i++)
#pragma unroll
        for (int v = 0; v < 4; v++) acc[i][v] = 0.f;

    for (int kt = 0; kt < 16; kt++) {
        const int cur = kt & 1;
        if (kt + 1 < 16) {
            const int nxt = (kt + 1) & 1;
            const size_t koff = ((size_t)(b * LSEQ + (kt + 1) * 64) * kvstride) + h * HDIM;
            for (int t = tid; t < 512; t += 256) {
                int row = t >> 3, ch = t & 7;
                cpa16(ksb + nxt * KV_BUF * 2 + row * (AST * 2) + ch * 16,
                      kp + koff + (size_t)row * kvstride + ch * 8);
                cpa16(vsb + nxt * KV_BUF * 2 + row * (AST * 2) + ch * 16,
                      vp + koff + (size_t)row * kvstride + ch * 8);
            }
            asm volatile("cp.async.commit_group;");
            asm volatile("cp.async.wait_group 1;");
        } else {
            asm volatile("cp.async.wait_group 0;");
        }
        __syncthreads();
        if (kt + 1 < 16 && tid < 64) {
            int kidx = (kt + 1) * 64 + tid;
            int msk = em[b * LSEQ + kidx];
            if (ap && kidx == LSEQ - 1) msk = 0;
            mk[((kt + 1) & 1) * 64 + tid] = msk ? 1.0f : 0.0f;
        }

        const uint32_t kb = ksb + cur * KV_BUF * 2;
        const uint32_t vb = vsb + cur * KV_BUF * 2;
        const float* mkc = mk + cur * 64;

        float s[8][4];
#pragma unroll
        for (int i = 0; i < 8; i++)
#pragma unroll
            for (int v = 0; v < 4; v++) s[i][v] = 0.f;
#pragma unroll
        for (int c = 0; c < 4; c++) {
#pragma unroll
            for (int ng = 0; ng < 4; ng++) {
                uint32_t bf[4];
                int n = 16 * ng + r8 + (grp >> 1) * 8;
                int kk = 16 * c + (grp & 1) * 8;
                ldmat_x4(bf, kb + (n * AST + kk) * 2);
                uint32_t b0[2] = {bf[0], bf[1]};
                uint32_t b1[2] = {bf[2], bf[3]};
                mma_f16(s[2 * ng], qf[c], b0);
                mma_f16(s[2 * ng + 1], qf[c], b1);
            }
        }

#pragma unroll
        for (int ni = 0; ni < 8; ni++) {
            int c0 = ni * 8 + tg * 2;
            float k0 = mkc[c0], k1 = mkc[c0 + 1];
            s[ni][0] = (k0 != 0.f) ? -10000.f : s[ni][0] * ATT_SCALE;
            s[ni][1] = (k1 != 0.f) ? -10000.f : s[ni][1] * ATT_SCALE;
            s[ni][2] = (k0 != 0.f) ? -10000.f : s[ni][2] * ATT_SCALE;
            s[ni][3] = (k1 != 0.f) ? -10000.f : s[ni][3] * ATT_SCALE;
        }

        float mt0 = -1e30f, mt1 = -1e30f;
#pragma unroll
        for (int ni = 0; ni < 8; ni++) {
            mt0 = fmaxf(mt0, fmaxf(s[ni][0], s[ni][1]));
            mt1 = fmaxf(mt1, fmaxf(s[ni][2], s[ni][3]));
        }
        mt0 = fmaxf(mt0, __shfl_xor_sync(0xffffffffu, mt0, 1));
        mt0 = fmaxf(mt0, __shfl_xor_sync(0xffffffffu, mt0, 2));
        mt1 = fmaxf(mt1, __shfl_xor_sync(0xffffffffu, mt1, 1));
        mt1 = fmaxf(mt1, __shfl_xor_sync(0xffffffffu, mt1, 2));
        float nm0 = fmaxf(m0, mt0), nm1 = fmaxf(m1, mt1);
        float a0 = __expf(m0 - nm0), a1 = __expf(m1 - nm1);

        uint32_t pa[8], pb[8];
        float sum0 = 0.f, sum1 = 0.f;
#pragma unroll
        for (int ni = 0; ni < 8; ni++) {
            __half2 hA = __floats2half2_rn(__expf(s[ni][0] - nm0), __expf(s[ni][1] - nm0));
            __half2 hB = __floats2half2_rn(__expf(s[ni][2] - nm1), __expf(s[ni][3] - nm1));
            pa[ni] = *(uint32_t*)&hA;
            pb[ni] = *(uint32_t*)&hB;
            sum0 += __low2float(hA) + __high2float(hA);
            sum1 += __low2float(hB) + __high2float(hB);
        }
        sum0 += __shfl_xor_sync(0xffffffffu, sum0, 1);
        sum0 += __shfl_xor_sync(0xffffffffu, sum0, 2);
        sum1 += __shfl_xor_sync(0xffffffffu, sum1, 1);
        sum1 += __shfl_xor_sync(0xffffffffu, sum1, 2);
        m0 = nm0; m1 = nm1;
        l0 = l0 * a0 + sum0;
        l1 = l1 * a1 + sum1;
#pragma unroll
        for (int ni = 0; ni < 8; ni++) {
            acc[ni][0] *= a0; acc[ni][1] *= a0;
            acc[ni][2] *= a1; acc[ni][3] *= a1;
        }

#pragma unroll
        for (int c = 0; c < 4; c++) {
            uint32_t af[4] = {pa[2 * c], pb[2 * c], pa[2 * c + 1], pb[2 * c + 1]};
#pragma unroll
            for (int dg = 0; dg < 4; dg++) {
                uint32_t bf[4];
                int j = 16 * c + r8 + (grp & 1) * 8;
                int d = 16 * dg + (grp >> 1) * 8;
                ldmat_x4t(bf, vb + (j * AST + d) * 2);
                uint32_t b0[2] = {bf[0], bf[1]};
                uint32_t b1[2] = {bf[2], bf[3]};
                mma_f16(acc[2 * dg], af, b0);
                mma_f16(acc[2 * dg + 1], af, b1);
            }
        }
        __syncthreads();
    }

    float i0v = 1.0f / l0, i1v = 1.0f / l1;
    int r0 = q0 + 16 * warp + g;
#pragma unroll
    for (int ni = 0; ni < 8; ni++) {
        int cc = h * HDIM + ni * 8 + tg * 2;
        *(__half2*)(out + (size_t)(b * LSEQ + r0) * DMODEL + cc) =
            __floats2half2_rn(acc[ni][0] * i0v, acc[ni][1] * i0v);
        *(__half2*)(out + (size_t)(b * LSEQ + r0 + 8) * DMODEL + cc) =
            __floats2half2_rn(acc[ni][2] * i1v, acc[ni][3] * i1v);
    }
}

// ---------------- LayerNorm over half input ---------------------------------
__global__ __launch_bounds__(256) void ln_h(
    const __half* __restrict__ X, const float* __restrict__ gam,
    const float* __restrict__ bet, __half* __restrict__ Yh, float* __restrict__ Yf) {
    __shared__ float red[8];
    __shared__ float sMean, sVar;
    const int row = blockIdx.x;
    const int tid = threadIdx.x;
    const __half2* x2 = (const __half2*)(X + (size_t)row * DMODEL);
    __half2 h0 = x2[tid * 2];
    __half2 h1 = x2[tid * 2 + 1];
    float vx = __low2float(h0), vy = __high2float(h0);
    float vz = __low2float(h1), vw = __high2float(h1);
    float s = vx + vy + vz + vw;
#pragma unroll
    for (int o = 16; o; o >>= 1) s += __shfl_xor_sync(0xffffffffu, s, o);
    int w = tid >> 5, lane = tid & 31;
    if (lane == 0) red[w] = s;
    __syncthreads();
    if (tid == 0) {
        float t = 0;
#pragma unroll
        for (int i = 0; i < 8; i++) t += red[i];
        sMean = t * (1.0f / DMODEL);
    }
    __syncthreads();
    float m = sMean;
    float dx = vx - m, dy = vy - m, dz = vz - m, dw = vw - m;
    float qv = dx * dx + dy * dy + dz * dz + dw * dw;
#pragma unroll
    for (int o = 16; o; o >>= 1) qv += __shfl_xor_sync(0xffffffffu, qv, o);
    if (lane == 0) red[w] = qv;
    __syncthreads();
    if (tid == 0) {
        float t = 0;
#pragma unroll
        for (int i = 0; i < 8; i++) t += red[i];
        sVar = t * (1.0f / DMODEL);
    }
    __syncthreads();
    float inv = rsqrtf(sVar + LN_EPS);
    float4 gv = *(const float4*)(gam + tid * 4);
    float4 bv = *(const float4*)(bet + tid * 4);
    float ox = dx * inv * gv.x + bv.x;
    float oy = dy * inv * gv.y + bv.y;
    float oz = dz * inv * gv.z + bv.z;
    float ow = dw * inv * gv.w + bv.w;
    if (Yh) {
        __half2* yh = (__half2*)(Yh + (size_t)row * DMODEL + tid * 4);
        yh[0] = __floats2half2_rn(ox, oy);
        yh[1] = __floats2half2_rn(oz, ow);
    }
    if (Yf) {
        *(float4*)(Yf + (size_t)row * DMODEL + tid * 4) = make_float4(ox, oy, oz, ow);
    }
}

// ---------------- launch ----------------------------------------------------
extern "C" void kernel_launch(void* const* d_in, const int* in_sizes, int n_in,
                              void* d_out, int out_size) {
    const float* q  = (const float*)d_in[0];
    const float* kv = (const float*)d_in[1];
    const unsigned char* kvm = (const unsigned char*)d_in[2];
    const float* Wq = (const float*)d_in[3];
    const float* bq = (const float*)d_in[4];
    const float* Wk = (const float*)d_in[5];
    const float* bk = (const float*)d_in[6];
    const float* Wv = (const float*)d_in[7];
    const float* bv = (const float*)d_in[8];
    const float* Wo = (const float*)d_in[9];
    const float* bo = (const float*)d_in[10];
    const float* ln1g = (const float*)d_in[11];
    const float* ln1b = (const float*)d_in[12];
    const float* W1 = (const float*)d_in[13];
    const float* b1 = (const float*)d_in[14];
    const float* W2 = (const float*)d_in[15];
    const float* b2 = (const float*)d_in[16];
    const float* ln2g = (const float*)d_in[17];
    const float* ln2b = (const float*)d_in[18];
    float* out = (float*)d_out;

    __half *qh, *kvh, *qph, *kvph, *atth, *xh, *yh, *hh;
    __half *wqh, *wkvh, *woh, *w1h, *w2h;
    float *bkv;
    int *allpad, *mstride;
    unsigned char* emask;
    cudaGetSymbolAddress((void**)&qh, g_qh);
    cudaGetSymbolAddress((void**)&kvh, g_kvh);
    cudaGetSymbolAddress((void**)&qph, g_qph);
    cudaGetSymbolAddress((void**)&kvph, g_kvph);
    cudaGetSymbolAddress((void**)&atth, g_atth);
    cudaGetSymbolAddress((void**)&xh, g_xh);
    cudaGetSymbolAddress((void**)&yh, g_yh);
    cudaGetSymbolAddress((void**)&hh, g_hh);
    cudaGetSymbolAddress((void**)&wqh, g_wqh);
    cudaGetSymbolAddress((void**)&wkvh, g_wkvh);
    cudaGetSymbolAddress((void**)&woh, g_woh);
    cudaGetSymbolAddress((void**)&w1h, g_w1h);
    cudaGetSymbolAddress((void**)&w2h, g_w2h);
    cudaGetSymbolAddress((void**)&bkv, g_bkv);
    cudaGetSymbolAddress((void**)&allpad, g_allpad);
    cudaGetSymbolAddress((void**)&emask, g_emask);
    cudaGetSymbolAddress((void**)&mstride, g_mstride);

    cudaFuncSetAttribute(hgemm, cudaFuncAttributeMaxDynamicSharedMemorySize, HG_SMEM);
    cudaFuncSetAttribute(attn_fa, cudaFuncAttributeMaxDynamicSharedMemorySize, ATT2_SMEM);

    dim3 blk(256);
    const int DD4 = DMODEL * DMODEL / 4;
    const int HR4 = HALF_ROWS * DMODEL / 4;

    cudaStream_t side;
    cudaStreamCreateWithFlags(&side, cudaStreamNonBlocking);
    cudaEvent_t evStart, evCommon, evW, evMask, evDone1;
    cudaEventCreateWithFlags(&evStart, cudaEventDisableTiming);
    cudaEventCreateWithFlags(&evCommon, cudaEventDisableTiming);
    cudaEventCreateWithFlags(&evW, cudaEventDisableTiming);
    cudaEventCreateWithFlags(&evMask, cudaEventDisableTiming);
    cudaEventCreateWithFlags(&evDone1, cudaEventDisableTiming);

    // fork
    cudaEventRecord(evStart, 0);
    cudaStreamWaitEvent(side, evStart, 0);

    // ---- MAIN (stream 0): minimal common prep for projections ----
    f32_to_f16<<<(DD4 + 255) / 256, 256>>>(Wq, wqh, DD4);
    pack_kv_h<<<(DMODEL * 2 * DMODEL / 4 + 255) / 256, 256>>>(Wk, Wv, wkvh);
    pack_bias2<<<(DMODEL + 255) / 256, 256>>>(bk, bv, bkv);
    cudaEventRecord(evCommon, 0);

    // ---- SIDE: Wo/FFN weight conversions + mask prep (off main's path) ----
    f32_to_f16<<<(DD4 + 255) / 256, 256, 0, side>>>(Wo, woh, DD4);
    f32_to_f16<<<(DMODEL * DFF / 4 + 255) / 256, 256, 0, side>>>(W1, w1h, DMODEL * DFF / 4);
    f32_to_f16<<<(DMODEL * DFF / 4 + 255) / 256, 256, 0, side>>>(W2, w2h, DMODEL * DFF / 4);
    cudaEventRecord(evW, side);
    detect_mask_stride<<<1, 256, 0, side>>>(kvm, mstride);
    mask_prep<<<BATCH, 256, 0, side>>>(kvm, mstride, emask, allpad);
    cudaEventRecord(evMask, side);
    cudaStreamWaitEvent(side, evCommon, 0);

    // ======== chain pieces ========
    // PREG: input conversions + Q/KV projections (no masks / FFN weights)
#define CHAIN_PREG(c, st)                                                         \
    do {                                                                          \
        const size_t r0 = (size_t)(c) * HALF_ROWS;                                \
        f32_to_f16<<<(HR4 + 255) / 256, 256, 0, (st)>>>(                          \
            q + r0 * DMODEL, qh + r0 * DMODEL, HR4);                              \
        f32_to_f16<<<(HR4 + 255) / 256, 256, 0, (st)>>>(                          \
            kv + r0 * DMODEL, kvh + r0 * DMODEL, HR4);                            \
        hgemm<<<dim3(8, HALF_ROWS / 128), blk, HG_SMEM, (st)>>>(                  \
            qh + r0 * DMODEL, wqh, bq, nullptr, nullptr, nullptr,                 \
            qph + r0 * DMODEL, HALF_ROWS, DMODEL, DMODEL, 0);                     \
        hgemm<<<dim3(16, HALF_ROWS / 128), blk, HG_SMEM, (st)>>>(                 \
            kvh + r0 * DMODEL, wkvh, bkv, nullptr, nullptr, nullptr,              \
            kvph + r0 * 2 * DMODEL, HALF_ROWS, 2 * DMODEL, DMODEL, 0);            \
    } while (0)

#define CHAIN_ATTN(c, st)                                                         \
    do {                                                                          \
        const size_t r0 = (size_t)(c) * HALF_ROWS;                                \
        attn_fa<<<dim3(LSEQ / 128, NHEAD, HALF_B), blk, ATT2_SMEM, (st)>>>(       \
            qph + r0 * DMODEL, kvph + r0 * 2 * DMODEL,                            \
            kvph + r0 * 2 * DMODEL + DMODEL, emask + r0, allpad + (c) * HALF_B,   \
            atth + r0 * DMODEL, 2 * DMODEL);                                      \
    } while (0)

    // POST: Wo + residual(q fp32) -> yh; LN1 -> xh; FFN1 -> hh;
    //       FFN2 + residual(xh) -> yh; LN2 -> out (fp32)
#define CHAIN_POST(c, st)                                                         \
    do {                                                                          \
        const size_t r0 = (size_t)(c) * HALF_ROWS;                                \
        hgemm<<<dim3(8, HALF_ROWS / 128), blk, HG_SMEM, (st)>>>(                  \
            atth + r0 * DMODEL, woh, bo, q + r0 * DMODEL, nullptr, nullptr,       \
            yh + r0 * DMODEL, HALF_ROWS, DMODEL, DMODEL, 0);                      \
        ln_h<<<HALF_ROWS, blk, 0, (st)>>>(                                        \
            yh + r0 * DMODEL, ln1g, ln1b, xh + r0 * DMODEL, nullptr);             \
        hgemm<<<dim3(32, HALF_ROWS / 128), blk, HG_SMEM, (st)>>>(                 \
            xh + r0 * DMODEL, w1h, b1, nullptr, nullptr, nullptr,                 \
            hh + r0 * DFF, HALF_ROWS, DFF, DMODEL, 1);                            \
        hgemm<<<dim3(8, HALF_ROWS / 128), blk, HG_SMEM, (st)>>>(                  \
            hh + r0 * DFF, w2h, b2, nullptr, xh + r0 * DMODEL, nullptr,           \
            yh + r0 * DMODEL, HALF_ROWS, DMODEL, DFF, 0);                         \
        ln_h<<<HALF_ROWS, blk, 0, (st)>>>(                                        \
            yh + r0 * DMODEL, ln2g, ln2b, nullptr, out + r0 * DMODEL);            \
    } while (0)

    // chain0 on main: projections immediately; masks awaited only at attention;
    // Wo/FFN weights awaited only at POST.
    CHAIN_PREG(0, 0);
    cudaStreamWaitEvent(0, evMask, 0);
    CHAIN_ATTN(0, 0);
    cudaStreamWaitEvent(0, evW, 0);
    CHAIN_POST(0, 0);

    // chain1 on side: weight convs + masks + evCommon already ordered in-stream.
    CHAIN_PREG(1, side);
    CHAIN_ATTN(1, side);
    CHAIN_POST(1, side);
    cudaEventRecord(evDone1, side);

    // join
    cudaStreamWaitEvent(0, evDone1, 0);
#undef CHAIN_PREG
#undef CHAIN_ATTN
#undef CHAIN_POST
}